// round 10
// baseline (speedup 1.0000x reference)
#include <cuda_runtime.h>
#include <math.h>
#include <stdint.h>

#define B_ 256
#define N_ 2048
#define M_ 64
#define H_ 512
#define EPS_ 1e-8f

// d_out float offsets: out, reads, h, c, weights, new_mem
#define OFF_OUT   0
#define OFF_READS 32768
#define OFF_H     65536
#define OFF_C     196608
#define OFF_W     327680
#define OFF_MEM   1900544

__device__ float g_gates4[4 * B_ * 2048];   // split-k partials for gates
__device__ float g_p8[8 * B_ * 352];        // split-k partials for head params

__device__ __forceinline__ float sigf(float x) { return 1.0f / (1.0f + expf(-x)); }
__device__ __forceinline__ float softplusf(float x) { return fmaxf(x, 0.0f) + log1pf(expf(-fabsf(x))); }

union U64F2 { unsigned long long u; float2 f; };
__device__ __forceinline__ void ffma2(unsigned long long& d, unsigned long long a, unsigned long long b) {
    asm("fma.rn.f32x2 %0, %1, %2, %0;" : "+l"(d) : "l"(a), "l"(b));
}

// gather a float4 of the concatenated LSTM input x = [inp(128) | r0(64) | r1(64) | h(512)]
__device__ __forceinline__ float4 xcat4(const float* __restrict__ inp,
                                        const float* __restrict__ pr,
                                        const float* __restrict__ ph,
                                        int b, int k) {
    const float* src;
    if (k < 128) src = inp + b * 128 + k;
    else if (k < 192) src = pr + b * 64 + (k - 128);
    else if (k < 256) src = pr + 16384 + b * 64 + (k - 192);
    else src = ph + b * 512 + (k - 256);
    return *(const float4*)src;
}

// ---------------- K1: gates GEMM, k-pair f32x2, split-k=4, fused input gather ----------------
__global__ void __launch_bounds__(256, 2) k1_gates(const float* __restrict__ inp,
                                                   const float* __restrict__ prev_reads,
                                                   const float* __restrict__ prev_h,
                                                   const float* __restrict__ Wih,
                                                   const float* __restrict__ Whh) {
    __shared__ float As[2][64][20];
    __shared__ float Bs[2][128][20];
    int tid = threadIdx.x;
    int j0 = blockIdx.x * 128, b0 = blockIdx.y * 64, ks = blockIdx.z;
    int k_base = ks * 192;
    int tx = tid & 15, ty = tid >> 4;

    int arow = tid >> 2, ak4 = tid & 3;
    int bj0 = tid >> 2, bk4 = tid & 3;

    unsigned long long acc[4][8];
#pragma unroll
    for (int i = 0; i < 4; i++)
#pragma unroll
        for (int j = 0; j < 8; j++) acc[i][j] = 0ull;

    float4 fa, fb0, fb1;
    {
        fa = xcat4(inp, prev_reads, prev_h, b0 + arow, k_base + ak4 * 4);
        int kgb = k_base + bk4 * 4;
        int j1 = j0 + bj0, j2 = j0 + bj0 + 64;
        fb0 = *(const float4*)((kgb < 256) ? (Wih + (size_t)j1 * 256 + kgb) : (Whh + (size_t)j1 * 512 + kgb - 256));
        fb1 = *(const float4*)((kgb < 256) ? (Wih + (size_t)j2 * 256 + kgb) : (Whh + (size_t)j2 * 512 + kgb - 256));
    }
    *(float4*)&As[0][arow][ak4 * 4] = fa;
    *(float4*)&Bs[0][bj0][bk4 * 4] = fb0;
    *(float4*)&Bs[0][bj0 + 64][bk4 * 4] = fb1;
    __syncthreads();

    for (int s = 0; s < 12; s++) {
        int cur = s & 1;
        if (s + 1 < 12) {
            fa = xcat4(inp, prev_reads, prev_h, b0 + arow, k_base + (s + 1) * 16 + ak4 * 4);
            int kgb = k_base + (s + 1) * 16 + bk4 * 4;
            int j1 = j0 + bj0, j2 = j0 + bj0 + 64;
            fb0 = *(const float4*)((kgb < 256) ? (Wih + (size_t)j1 * 256 + kgb) : (Whh + (size_t)j1 * 512 + kgb - 256));
            fb1 = *(const float4*)((kgb < 256) ? (Wih + (size_t)j2 * 256 + kgb) : (Whh + (size_t)j2 * 512 + kgb - 256));
        }
        const float* As_ = &As[cur][0][0];
        const float* Bs_ = &Bs[cur][0][0];
#pragma unroll
        for (int kg = 0; kg < 4; kg++) {
            ulonglong2 au[4];
#pragma unroll
            for (int i = 0; i < 4; i++)
                au[i] = *(const ulonglong2*)(As_ + (ty * 4 + i) * 20 + kg * 4);
#pragma unroll
            for (int jj = 0; jj < 8; jj++) {
                ulonglong2 bu = *(const ulonglong2*)(Bs_ + (tx + 16 * jj) * 20 + kg * 4);
#pragma unroll
                for (int i = 0; i < 4; i++) {
                    ffma2(acc[i][jj], au[i].x, bu.x);
                    ffma2(acc[i][jj], au[i].y, bu.y);
                }
            }
        }
        if (s + 1 < 12) {
            int nxt = (s + 1) & 1;
            *(float4*)&As[nxt][arow][ak4 * 4] = fa;
            *(float4*)&Bs[nxt][bj0][bk4 * 4] = fb0;
            *(float4*)&Bs[nxt][bj0 + 64][bk4 * 4] = fb1;
        }
        __syncthreads();
    }

    float* outp = g_gates4 + (size_t)ks * B_ * 2048;
#pragma unroll
    for (int i = 0; i < 4; i++) {
        int row = (b0 + ty * 4 + i) * 2048 + j0 + tx;
#pragma unroll
        for (int jj = 0; jj < 8; jj++) {
            U64F2 u; u.u = acc[i][jj];
            outp[row + 16 * jj] = u.f.x + u.f.y;
        }
    }
}

// ---------------- K1b: sum partials + LSTM elementwise ----------------
__global__ void k1b_lstm(const float* __restrict__ blstm,
                         const float* __restrict__ prev_c,
                         float* __restrict__ dout) {
    int idx = blockIdx.x * 256 + threadIdx.x;
    int b = idx >> 9, hh = idx & 511;
    float gi = blstm[hh], gf = blstm[512 + hh], gg = blstm[1024 + hh], go = blstm[1536 + hh];
#pragma unroll
    for (int p = 0; p < 4; p++) {
        const float* gr = g_gates4 + (size_t)p * B_ * 2048 + b * 2048;
        gi += gr[hh]; gf += gr[512 + hh]; gg += gr[1024 + hh]; go += gr[1536 + hh];
    }
    float c = sigf(gf) * prev_c[idx] + sigf(gi) * tanhf(gg);
    float h = sigf(go) * tanhf(c);
    dout[OFF_C + idx] = c;
    dout[OFF_H + idx] = h;
}

// ---------------- K2: head-param GEMM, 64col x 64b tiles, single k-slab 64, split-k=8 ----------------
__global__ void __launch_bounds__(256) k2_p(const float* __restrict__ readW,
                                            const float* __restrict__ writeW,
                                            const float* __restrict__ dout) {
    __shared__ float Hst[64][68];
    __shared__ float Wst[64][68];
    int tid = threadIdx.x;
    int c0 = blockIdx.x * 64, b0 = blockIdx.y * 64, ks = blockIdx.z;
    int kofs = ks * 64;
    int tx = tid & 15, ty = tid >> 4;

    int lrow = tid >> 2, lk16 = (tid & 3) * 16;
    {
        const float* hrow = dout + OFF_H + (b0 + lrow) * 512 + kofs + lk16;
        int col_l = c0 + lrow;
        const float* wrow = 0;
        if (col_l < 140) wrow = readW + (size_t)col_l * 512 + kofs + lk16;
        else if (col_l < 338) wrow = writeW + (size_t)(col_l - 140) * 512 + kofs + lk16;
#pragma unroll
        for (int q = 0; q < 4; q++) {
            float4 hv = *(const float4*)(hrow + 4 * q);
            float4 wv = wrow ? *(const float4*)(wrow + 4 * q) : make_float4(0.f, 0.f, 0.f, 0.f);
#pragma unroll
            for (int c = 0; c < 4; c++) {
                Hst[lk16 + 4 * q + c][lrow] = (&hv.x)[c];
                Wst[lk16 + 4 * q + c][lrow] = (&wv.x)[c];
            }
        }
    }
    __syncthreads();

    float acc[4][4] = {};
#pragma unroll 8
    for (int kk = 0; kk < 64; kk++) {
        float4 h4 = *(const float4*)&Hst[kk][ty * 4];
        float4 w4 = *(const float4*)&Wst[kk][tx * 4];
#pragma unroll
        for (int i = 0; i < 4; i++)
#pragma unroll
            for (int j = 0; j < 4; j++)
                acc[i][j] = fmaf((&h4.x)[i], (&w4.x)[j], acc[i][j]);
    }

    float* outp = g_p8 + (size_t)ks * B_ * 352;
#pragma unroll
    for (int i = 0; i < 4; i++) {
#pragma unroll
        for (int j = 0; j < 4; j++) {
            int col = c0 + tx * 4 + j;
            if (col < 338)
                outp[(size_t)(b0 + ty * 4 + i) * 352 + col] = acc[i][j];
        }
    }
}

// ---------------- block reductions (256 threads, 8 warps) ----------------
__device__ __forceinline__ float blk_red_sum8(float v, volatile float* red) {
    int lane = threadIdx.x & 31, w = threadIdx.x >> 5;
#pragma unroll
    for (int o = 16; o; o >>= 1) v += __shfl_xor_sync(0xffffffffu, v, o);
    if (lane == 0) red[w] = v;
    __syncthreads();
    if (w == 0) {
        float x = (lane < 8) ? red[lane] : 0.f;
#pragma unroll
        for (int o = 4; o; o >>= 1) x += __shfl_xor_sync(0xffffffffu, x, o);
        if (lane == 0) red[0] = x;
    }
    __syncthreads();
    float r = red[0];
    __syncthreads();
    return r;
}
__device__ __forceinline__ float blk_red_max8(float v, volatile float* red) {
    int lane = threadIdx.x & 31, w = threadIdx.x >> 5;
#pragma unroll
    for (int o = 16; o; o >>= 1) v = fmaxf(v, __shfl_xor_sync(0xffffffffu, v, o));
    if (lane == 0) red[w] = v;
    __syncthreads();
    if (w == 0) {
        float x = (lane < 8) ? red[lane] : -3.0e38f;
#pragma unroll
        for (int o = 4; o; o >>= 1) x = fmaxf(x, __shfl_xor_sync(0xffffffffu, x, o));
        if (lane == 0) red[0] = x;
    }
    __syncthreads();
    float r = red[0];
    __syncthreads();
    return r;
}

// sum 8 split-k partials of head params
__device__ __forceinline__ float Psum(int b, int col) {
    float v = 0.f;
#pragma unroll
    for (int p = 0; p < 8; p++)
        v += g_p8[(size_t)p * B_ * 352 + (size_t)b * 352 + col];
    return v;
}

// ---------------- K34: fused addressing + read/write, 256 thr, 4 blocks/SM ----------------
__global__ void __launch_bounds__(256, 4) k34_fused(const float* __restrict__ mem,
                                                    const float* __restrict__ prev_ws,
                                                    const float* __restrict__ readb,
                                                    const float* __restrict__ writeb,
                                                    float* __restrict__ dout) {
    __shared__ float sim_s[3 * 2048];   // sims -> gated weights (per head) -> final weights
    __shared__ float wgs[2048];         // gated-weight scratch / partial-read buffer
    __shared__ float ksm[3 * 64];
    __shared__ float red[8];
    __shared__ float hp[3][6];
    __shared__ __align__(16) float es[64];
    __shared__ __align__(16) float as_[64];
    int b = blockIdx.x;
    int tid = threadIdx.x;
    int lane = tid & 31, wrp = tid >> 5;

    // ---- prologue ----
    if (tid < 192) {
        int h = tid >> 6, m = tid & 63;
        int base = (h < 2) ? h * 70 : 140;
        float bias = (h < 2) ? readb[base + m] : writeb[m];
        ksm[h * 64 + m] = tanhf(Psum(b, base + m) + bias);
    }
    if (tid < 64) {
        es[tid] = sigf(Psum(b, 210 + tid) + writeb[70 + tid]);
    } else if (tid < 128) {
        int t = tid - 64;
        as_[t] = Psum(b, 274 + t) + writeb[134 + t];
    }
    if (tid >= 128 && tid < 131) {
        int h = tid - 128;
        int base = (h < 2) ? h * 70 : 140;
        const float* bb = (h < 2) ? (readb + base) : writeb;
        float p64 = Psum(b, base + 64) + bb[64];
        float p65 = Psum(b, base + 65) + bb[65];
        float q0 = Psum(b, base + 66) + bb[66];
        float q1 = Psum(b, base + 67) + bb[67];
        float q2 = Psum(b, base + 68) + bb[68];
        float p69 = Psum(b, base + 69) + bb[69];
        hp[h][0] = softplusf(p64);
        hp[h][1] = sigf(p65);
        float mx = fmaxf(q0, fmaxf(q1, q2));
        float e0 = expf(q0 - mx), e1 = expf(q1 - mx), e2 = expf(q2 - mx);
        float si = 1.0f / (e0 + e1 + e2);
        hp[h][2] = e0 * si; hp[h][3] = e1 * si; hp[h][4] = e2 * si;
        hp[h][5] = 1.0f + softplusf(p69);
    }
    __syncthreads();

    // ---- phase B: stream memory ascending, cosine sims (8 lanes per row) ----
    int q = lane >> 3, s = lane & 7, m0 = s * 8;
    float kreg[3][8];
#pragma unroll
    for (int h = 0; h < 3; h++)
#pragma unroll
        for (int i = 0; i < 8; i++) kreg[h][i] = ksm[h * 64 + m0 + i];
    float kn[3];
#pragma unroll
    for (int h = 0; h < 3; h++) {
        float sq = 0.f;
#pragma unroll
        for (int i = 0; i < 8; i++) sq = fmaf(kreg[h][i], kreg[h][i], sq);
        sq += __shfl_xor_sync(0xffffffffu, sq, 1);
        sq += __shfl_xor_sync(0xffffffffu, sq, 2);
        sq += __shfl_xor_sync(0xffffffffu, sq, 4);
        kn[h] = sqrtf(sq);
    }

    const float* mb = mem + (size_t)b * N_ * M_;
    // 8 warps x 4 rows = 32 rows per slot; 64 slots; process 2 slots per iter (4 LDG.128 in flight)
    for (int it = 0; it < 64; it += 2) {
        int na = it * 32 + wrp * 4 + q;
        int nb2 = na + 32;
        float4 va0 = *(const float4*)(mb + na * 64 + m0);
        float4 va1 = *(const float4*)(mb + na * 64 + m0 + 4);
        float4 vb0 = *(const float4*)(mb + nb2 * 64 + m0);
        float4 vb1 = *(const float4*)(mb + nb2 * 64 + m0 + 4);
#pragma unroll
        for (int half = 0; half < 2; half++) {
            float4 v0 = half ? vb0 : va0;
            float4 v1 = half ? vb1 : va1;
            int n = half ? nb2 : na;
            float d0 = 0.f, d1 = 0.f, d2 = 0.f, ss = 0.f;
#pragma unroll
            for (int j = 0; j < 8; j++) {
                float x = (j < 4) ? (&v0.x)[j] : (&v1.x)[j - 4];
                d0 = fmaf(kreg[0][j], x, d0);
                d1 = fmaf(kreg[1][j], x, d1);
                d2 = fmaf(kreg[2][j], x, d2);
                ss = fmaf(x, x, ss);
            }
            d0 += __shfl_xor_sync(0xffffffffu, d0, 1); d0 += __shfl_xor_sync(0xffffffffu, d0, 2); d0 += __shfl_xor_sync(0xffffffffu, d0, 4);
            d1 += __shfl_xor_sync(0xffffffffu, d1, 1); d1 += __shfl_xor_sync(0xffffffffu, d1, 2); d1 += __shfl_xor_sync(0xffffffffu, d1, 4);
            d2 += __shfl_xor_sync(0xffffffffu, d2, 1); d2 += __shfl_xor_sync(0xffffffffu, d2, 2); d2 += __shfl_xor_sync(0xffffffffu, d2, 4);
            ss += __shfl_xor_sync(0xffffffffu, ss, 1); ss += __shfl_xor_sync(0xffffffffu, ss, 2); ss += __shfl_xor_sync(0xffffffffu, ss, 4);
            if (s == 0) {
                float mn = sqrtf(ss);
                sim_s[0 * 2048 + n] = d0 / (kn[0] * mn + EPS_);
                sim_s[1 * 2048 + n] = d1 / (kn[1] * mn + EPS_);
                sim_s[2 * 2048 + n] = d2 / (kn[2] * mn + EPS_);
            }
        }
    }
    __syncthreads();

    // ---- phase C: per-head softmax / interpolate / shift / sharpen (8 n per thread) ----
    for (int h = 0; h < 3; h++) {
        float beta = hp[h][0], g = hp[h][1];
        float s0 = hp[h][2], s1 = hp[h][3], s2 = hp[h][4], gamma = hp[h][5];
        float z[8], lm = -3.0e38f;
#pragma unroll
        for (int j = 0; j < 8; j++) {
            int n = tid + j * 256;
            z[j] = beta * sim_s[h * 2048 + n];
            lm = fmaxf(lm, z[j]);
        }
        float mx = blk_red_max8(lm, red);
        float lsum = 0.f;
#pragma unroll
        for (int j = 0; j < 8; j++) { z[j] = __expf(z[j] - mx); lsum += z[j]; }
        float S = blk_red_sum8(lsum, red);
        float invS = 1.0f / S;
        const float* pwb = prev_ws + ((size_t)h * B_ + b) * N_;
#pragma unroll
        for (int j = 0; j < 8; j++) {
            int n = tid + j * 256;
            wgs[n] = fmaf(g, z[j] * invS, (1.0f - g) * __ldcs(&pwb[n]));
        }
        __syncthreads();
        float psum = 0.f;
#pragma unroll
        for (int j = 0; j < 8; j++) {
            int n = tid + j * 256;
            float wt = s0 * wgs[(n + 2047) & 2047] + s1 * wgs[n] + s2 * wgs[(n + 1) & 2047];
            z[j] = exp2f(gamma * __log2f(wt + EPS_));
            psum += z[j];
        }
        float S2 = blk_red_sum8(psum, red);
        float inv2 = 1.0f / (S2 + EPS_);
        float* wout = dout + OFF_W + ((size_t)h * B_ + b) * N_;
#pragma unroll
        for (int j = 0; j < 8; j++) {
            int n = tid + j * 256;
            float wv = z[j] * inv2;
            __stcs(&wout[n], wv);
            sim_s[h * 2048 + n] = wv;
        }
        __syncthreads();
    }

    // ---- phase D: memory write + weighted reads, reverse band order ----
    // 8 warps x 2 rows = 16 rows per band-slot; 128 slots; 4 in flight, descending
    int qd = lane >> 4, md = lane & 15;
    float4 e4 = *(const float4*)&es[md * 4];
    float4 a4 = *(const float4*)&as_[md * 4];
    float racc0[4] = {0.f, 0.f, 0.f, 0.f};
    float racc1[4] = {0.f, 0.f, 0.f, 0.f};
    const float4* msrc = (const float4*)(mem + (size_t)b * N_ * M_);
    float4* mdst = (float4*)(dout + OFF_MEM + (size_t)b * N_ * M_);

    for (int band = 124; band >= 0; band -= 4) {
        float4 v[4]; float w0[4], w1[4], ww[4]; int nn[4];
#pragma unroll
        for (int u = 3; u >= 0; u--) {
            int n = (band + u) * 16 + wrp * 2 + qd;
            nn[u] = n;
            v[u] = __ldcs(&msrc[n * 16 + md]);
        }
#pragma unroll
        for (int u = 0; u < 4; u++) {
            w0[u] = sim_s[nn[u]]; w1[u] = sim_s[2048 + nn[u]]; ww[u] = sim_s[4096 + nn[u]];
        }
#pragma unroll
        for (int u = 3; u >= 0; u--) {
            float4 nv;
            nv.x = fmaf(v[u].x, fmaf(-ww[u], e4.x, 1.0f), ww[u] * a4.x);
            nv.y = fmaf(v[u].y, fmaf(-ww[u], e4.y, 1.0f), ww[u] * a4.y);
            nv.z = fmaf(v[u].z, fmaf(-ww[u], e4.z, 1.0f), ww[u] * a4.z);
            nv.w = fmaf(v[u].w, fmaf(-ww[u], e4.w, 1.0f), ww[u] * a4.w);
            __stcs(&mdst[nn[u] * 16 + md], nv);
            racc0[0] = fmaf(w0[u], v[u].x, racc0[0]);
            racc0[1] = fmaf(w0[u], v[u].y, racc0[1]);
            racc0[2] = fmaf(w0[u], v[u].z, racc0[2]);
            racc0[3] = fmaf(w0[u], v[u].w, racc0[3]);
            racc1[0] = fmaf(w1[u], v[u].x, racc1[0]);
            racc1[1] = fmaf(w1[u], v[u].y, racc1[1]);
            racc1[2] = fmaf(w1[u], v[u].z, racc1[2]);
            racc1[3] = fmaf(w1[u], v[u].w, racc1[3]);
        }
    }
    // reduce across qd pair within warp
#pragma unroll
    for (int u = 0; u < 4; u++) {
        racc0[u] += __shfl_xor_sync(0xffffffffu, racc0[u], 16);
        racc1[u] += __shfl_xor_sync(0xffffffffu, racc1[u], 16);
    }
    __syncthreads();
    if (lane < 16) {
#pragma unroll
        for (int u = 0; u < 4; u++) {
            wgs[wrp * 128 + md * 4 + u] = racc0[u];
            wgs[wrp * 128 + 64 + md * 4 + u] = racc1[u];
        }
    }
    __syncthreads();
    if (tid < 128) {
        int h = tid >> 6, m = tid & 63;
        float sum = 0.f;
#pragma unroll
        for (int w = 0; w < 8; w++) sum += wgs[w * 128 + h * 64 + m];
        dout[OFF_READS + h * B_ * M_ + b * M_ + m] = sum;
    }
}

// ---------------- K5: output GEMM + sigmoid (4 b per block) ----------------
__global__ void __launch_bounds__(256) k5_out(const float* __restrict__ outW,
                                              const float* __restrict__ outb,
                                              float* __restrict__ dout) {
    __shared__ float Wst[128][68];
    __shared__ float xs[4][644];
    int tid = threadIdx.x;
    int b0 = blockIdx.x * 4;
    int o = tid & 127, half = tid >> 7;
    int lr = tid >> 1, c8 = (tid & 1) * 32;

    for (int idx = tid; idx < 4 * 640; idx += 256) {
        int bb = idx / 640, k = idx - bb * 640;
        int b = b0 + bb;
        float v;
        if (k < 512) v = dout[OFF_H + b * 512 + k];
        else if (k < 576) v = dout[OFF_READS + b * 64 + (k - 512)];
        else v = dout[OFF_READS + B_ * M_ + b * 64 + (k - 576)];
        xs[bb][k] = v;
    }

    float acc0 = 0.f, acc1 = 0.f;
    float4 pw[8];
#pragma unroll
    for (int i = 0; i < 8; i++) pw[i] = *(const float4*)(outW + lr * 640 + c8 + 4 * i);
    for (int kt = 0; kt < 10; kt++) {
        __syncthreads();
#pragma unroll
        for (int i = 0; i < 8; i++) *(float4*)&Wst[lr][c8 + 4 * i] = pw[i];
        __syncthreads();
        if (kt + 1 < 10) {
            int kb = (kt + 1) * 64;
#pragma unroll
            for (int i = 0; i < 8; i++) pw[i] = *(const float4*)(outW + lr * 640 + kb + c8 + 4 * i);
        }
        int kb = kt * 64;
#pragma unroll
        for (int k4 = 0; k4 < 16; k4++) {
            float4 wv = *(const float4*)&Wst[o][k4 * 4];
            float4 x0 = *(const float4*)&xs[half][kb + k4 * 4];
            float4 x1 = *(const float4*)&xs[half + 2][kb + k4 * 4];
            acc0 = fmaf(wv.x, x0.x, fmaf(wv.y, x0.y, fmaf(wv.z, x0.z, fmaf(wv.w, x0.w, acc0))));
            acc1 = fmaf(wv.x, x1.x, fmaf(wv.y, x1.y, fmaf(wv.z, x1.z, fmaf(wv.w, x1.w, acc1))));
        }
    }
    float bo = outb[o];
    dout[OFF_OUT + (b0 + half) * 128 + o] = sigf(acc0 + bo);
    dout[OFF_OUT + (b0 + half + 2) * 128 + o] = sigf(acc1 + bo);
}

extern "C" void kernel_launch(void* const* d_in, const int* in_sizes, int n_in,
                              void* d_out, int out_size) {
    const float* inp        = (const float*)d_in[0];
    const float* prev_reads = (const float*)d_in[1];
    const float* prev_h     = (const float*)d_in[2];
    const float* prev_c     = (const float*)d_in[3];
    const float* prev_ws    = (const float*)d_in[4];
    const float* memory     = (const float*)d_in[5];
    const float* W_ih       = (const float*)d_in[6];
    const float* W_hh       = (const float*)d_in[7];
    const float* b_lstm     = (const float*)d_in[8];
    const float* read_W     = (const float*)d_in[9];
    const float* read_b     = (const float*)d_in[10];
    const float* write_W    = (const float*)d_in[11];
    const float* write_b    = (const float*)d_in[12];
    const float* out_W      = (const float*)d_in[13];
    const float* out_b      = (const float*)d_in[14];
    float* dout = (float*)d_out;

    k1_gates<<<dim3(16, 4, 4), 256>>>(inp, prev_reads, prev_h, W_ih, W_hh);
    k1b_lstm<<<512, 256>>>(b_lstm, prev_c, dout);
    k2_p<<<dim3(6, 4, 8), 256>>>(read_W, write_W, dout);
    k34_fused<<<256, 256>>>(memory, prev_ws, read_b, write_b, dout);
    k5_out<<<64, 256>>>(out_W, out_b, dout);
}

// round 11
// speedup vs baseline: 1.1436x; 1.1436x over previous
#include <cuda_runtime.h>
#include <math.h>
#include <stdint.h>

#define B_ 256
#define N_ 2048
#define M_ 64
#define H_ 512
#define EPS_ 1e-8f

// d_out float offsets: out, reads, h, c, weights, new_mem
#define OFF_OUT   0
#define OFF_READS 32768
#define OFF_H     65536
#define OFF_C     196608
#define OFF_W     327680
#define OFF_MEM   1900544

__device__ float g_gates4[4 * B_ * 2048];   // split-k partials for gates
__device__ float g_p8[8 * B_ * 352];        // split-k partials for head params

__device__ __forceinline__ float sigf(float x) { return 1.0f / (1.0f + expf(-x)); }
__device__ __forceinline__ float softplusf(float x) { return fmaxf(x, 0.0f) + log1pf(expf(-fabsf(x))); }

union U64F2 { unsigned long long u; float2 f; };
__device__ __forceinline__ void ffma2(unsigned long long& d, unsigned long long a, unsigned long long b) {
    asm("fma.rn.f32x2 %0, %1, %2, %0;" : "+l"(d) : "l"(a), "l"(b));
}

// gather a float4 of the concatenated LSTM input x = [inp(128) | r0(64) | r1(64) | h(512)]
__device__ __forceinline__ float4 xcat4(const float* __restrict__ inp,
                                        const float* __restrict__ pr,
                                        const float* __restrict__ ph,
                                        int b, int k) {
    const float* src;
    if (k < 128) src = inp + b * 128 + k;
    else if (k < 192) src = pr + b * 64 + (k - 128);
    else if (k < 256) src = pr + 16384 + b * 64 + (k - 192);
    else src = ph + b * 512 + (k - 256);
    return *(const float4*)src;
}

// ---------------- K1: gates GEMM, k-pair f32x2, split-k=4, fused input gather ----------------
__global__ void __launch_bounds__(256, 2) k1_gates(const float* __restrict__ inp,
                                                   const float* __restrict__ prev_reads,
                                                   const float* __restrict__ prev_h,
                                                   const float* __restrict__ Wih,
                                                   const float* __restrict__ Whh) {
    __shared__ float As[2][64][20];
    __shared__ float Bs[2][128][20];
    int tid = threadIdx.x;
    int j0 = blockIdx.x * 128, b0 = blockIdx.y * 64, ks = blockIdx.z;
    int k_base = ks * 192;
    int tx = tid & 15, ty = tid >> 4;

    int arow = tid >> 2, ak4 = tid & 3;
    int bj0 = tid >> 2, bk4 = tid & 3;

    unsigned long long acc[4][8];
#pragma unroll
    for (int i = 0; i < 4; i++)
#pragma unroll
        for (int j = 0; j < 8; j++) acc[i][j] = 0ull;

    float4 fa, fb0, fb1;
    {
        fa = xcat4(inp, prev_reads, prev_h, b0 + arow, k_base + ak4 * 4);
        int kgb = k_base + bk4 * 4;
        int j1 = j0 + bj0, j2 = j0 + bj0 + 64;
        fb0 = *(const float4*)((kgb < 256) ? (Wih + (size_t)j1 * 256 + kgb) : (Whh + (size_t)j1 * 512 + kgb - 256));
        fb1 = *(const float4*)((kgb < 256) ? (Wih + (size_t)j2 * 256 + kgb) : (Whh + (size_t)j2 * 512 + kgb - 256));
    }
    *(float4*)&As[0][arow][ak4 * 4] = fa;
    *(float4*)&Bs[0][bj0][bk4 * 4] = fb0;
    *(float4*)&Bs[0][bj0 + 64][bk4 * 4] = fb1;
    __syncthreads();

    for (int s = 0; s < 12; s++) {
        int cur = s & 1;
        if (s + 1 < 12) {
            fa = xcat4(inp, prev_reads, prev_h, b0 + arow, k_base + (s + 1) * 16 + ak4 * 4);
            int kgb = k_base + (s + 1) * 16 + bk4 * 4;
            int j1 = j0 + bj0, j2 = j0 + bj0 + 64;
            fb0 = *(const float4*)((kgb < 256) ? (Wih + (size_t)j1 * 256 + kgb) : (Whh + (size_t)j1 * 512 + kgb - 256));
            fb1 = *(const float4*)((kgb < 256) ? (Wih + (size_t)j2 * 256 + kgb) : (Whh + (size_t)j2 * 512 + kgb - 256));
        }
        const float* As_ = &As[cur][0][0];
        const float* Bs_ = &Bs[cur][0][0];
#pragma unroll
        for (int kg = 0; kg < 4; kg++) {
            ulonglong2 au[4];
#pragma unroll
            for (int i = 0; i < 4; i++)
                au[i] = *(const ulonglong2*)(As_ + (ty * 4 + i) * 20 + kg * 4);
#pragma unroll
            for (int jj = 0; jj < 8; jj++) {
                ulonglong2 bu = *(const ulonglong2*)(Bs_ + (tx + 16 * jj) * 20 + kg * 4);
#pragma unroll
                for (int i = 0; i < 4; i++) {
                    ffma2(acc[i][jj], au[i].x, bu.x);
                    ffma2(acc[i][jj], au[i].y, bu.y);
                }
            }
        }
        if (s + 1 < 12) {
            int nxt = (s + 1) & 1;
            *(float4*)&As[nxt][arow][ak4 * 4] = fa;
            *(float4*)&Bs[nxt][bj0][bk4 * 4] = fb0;
            *(float4*)&Bs[nxt][bj0 + 64][bk4 * 4] = fb1;
        }
        __syncthreads();
    }

    float* outp = g_gates4 + (size_t)ks * B_ * 2048;
#pragma unroll
    for (int i = 0; i < 4; i++) {
        int row = (b0 + ty * 4 + i) * 2048 + j0 + tx;
#pragma unroll
        for (int jj = 0; jj < 8; jj++) {
            U64F2 u; u.u = acc[i][jj];
            outp[row + 16 * jj] = u.f.x + u.f.y;
        }
    }
}

// ---------------- K1b: sum partials + LSTM elementwise ----------------
__global__ void k1b_lstm(const float* __restrict__ blstm,
                         const float* __restrict__ prev_c,
                         float* __restrict__ dout) {
    int idx = blockIdx.x * 256 + threadIdx.x;
    int b = idx >> 9, hh = idx & 511;
    float gi = blstm[hh], gf = blstm[512 + hh], gg = blstm[1024 + hh], go = blstm[1536 + hh];
#pragma unroll
    for (int p = 0; p < 4; p++) {
        const float* gr = g_gates4 + (size_t)p * B_ * 2048 + b * 2048;
        gi += gr[hh]; gf += gr[512 + hh]; gg += gr[1024 + hh]; go += gr[1536 + hh];
    }
    float c = sigf(gf) * prev_c[idx] + sigf(gi) * tanhf(gg);
    float h = sigf(go) * tanhf(c);
    dout[OFF_C + idx] = c;
    dout[OFF_H + idx] = h;
}

// ---------------- K2: head-param GEMM, 64col x 64b tiles, single k-slab 64, split-k=8 ----------------
__global__ void __launch_bounds__(256) k2_p(const float* __restrict__ readW,
                                            const float* __restrict__ writeW,
                                            const float* __restrict__ dout) {
    __shared__ float Hst[64][68];   // [k][b]
    __shared__ float Wst[64][68];   // [k][col]
    int tid = threadIdx.x;
    int c0 = blockIdx.x * 64, b0 = blockIdx.y * 64, ks = blockIdx.z;
    int kofs = ks * 64;
    int tx = tid & 15, ty = tid >> 4;

    int lrow = tid >> 2, lk16 = (tid & 3) * 16;
    {
        const float* hrow = dout + OFF_H + (b0 + lrow) * 512 + kofs + lk16;
        int col_l = c0 + lrow;
        const float* wrow = 0;
        if (col_l < 140) wrow = readW + (size_t)col_l * 512 + kofs + lk16;
        else if (col_l < 338) wrow = writeW + (size_t)(col_l - 140) * 512 + kofs + lk16;
#pragma unroll
        for (int q = 0; q < 4; q++) {
            float4 hv = *(const float4*)(hrow + 4 * q);
            float4 wv = wrow ? *(const float4*)(wrow + 4 * q) : make_float4(0.f, 0.f, 0.f, 0.f);
#pragma unroll
            for (int c = 0; c < 4; c++) {
                Hst[lk16 + 4 * q + c][lrow] = (&hv.x)[c];
                Wst[lk16 + 4 * q + c][lrow] = (&wv.x)[c];
            }
        }
    }
    __syncthreads();

    float acc[4][4] = {};
#pragma unroll 8
    for (int kk = 0; kk < 64; kk++) {
        float4 h4 = *(const float4*)&Hst[kk][ty * 4];
        float4 w4 = *(const float4*)&Wst[kk][tx * 4];
#pragma unroll
        for (int i = 0; i < 4; i++)
#pragma unroll
            for (int j = 0; j < 4; j++)
                acc[i][j] = fmaf((&h4.x)[i], (&w4.x)[j], acc[i][j]);
    }

    float* outp = g_p8 + (size_t)ks * B_ * 352;
#pragma unroll
    for (int i = 0; i < 4; i++) {
#pragma unroll
        for (int j = 0; j < 4; j++) {
            int col = c0 + tx * 4 + j;
            if (col < 338)
                outp[(size_t)(b0 + ty * 4 + i) * 352 + col] = acc[i][j];
        }
    }
}

// ---------------- packed 3-value block sum reduction (512 threads) ----------------
__device__ __forceinline__ void blk_red_sum3(float v[3], volatile float* red) {
    int lane = threadIdx.x & 31, w = threadIdx.x >> 5;
#pragma unroll
    for (int o = 16; o; o >>= 1) {
        v[0] += __shfl_xor_sync(0xffffffffu, v[0], o);
        v[1] += __shfl_xor_sync(0xffffffffu, v[1], o);
        v[2] += __shfl_xor_sync(0xffffffffu, v[2], o);
    }
    if (lane == 0) { red[w] = v[0]; red[16 + w] = v[1]; red[32 + w] = v[2]; }
    __syncthreads();
    if (w == 0) {
        float x0 = (lane < 16) ? red[lane] : 0.f;
        float x1 = (lane < 16) ? red[16 + lane] : 0.f;
        float x2 = (lane < 16) ? red[32 + lane] : 0.f;
#pragma unroll
        for (int o = 8; o; o >>= 1) {
            x0 += __shfl_xor_sync(0xffffffffu, x0, o);
            x1 += __shfl_xor_sync(0xffffffffu, x1, o);
            x2 += __shfl_xor_sync(0xffffffffu, x2, o);
        }
        if (lane == 0) { red[0] = x0; red[16] = x1; red[32] = x2; }
    }
    __syncthreads();
    v[0] = red[0]; v[1] = red[16]; v[2] = red[32];
    __syncthreads();
}

// sum 8 split-k partials of head params
__device__ __forceinline__ float Psum(int b, int col) {
    float v = 0.f;
#pragma unroll
    for (int p = 0; p < 8; p++)
        v += g_p8[(size_t)p * B_ * 352 + (size_t)b * 352 + col];
    return v;
}

// ---------------- K34: fused addressing + read/write (one block per b, 2/SM) ----------------
__global__ void __launch_bounds__(512, 2) k34_fused(const float* __restrict__ mem,
                                                    const float* __restrict__ prev_ws,
                                                    const float* __restrict__ readb,
                                                    const float* __restrict__ writeb,
                                                    float* __restrict__ dout) {
    __shared__ float sim_s[3 * 2048];
    __shared__ float wgs[2048];
    __shared__ float ksm[3 * 64];
    __shared__ float red[48];
    __shared__ float hp[3][6];
    __shared__ __align__(16) float es[64];
    __shared__ __align__(16) float as_[64];
    int b = blockIdx.x;
    int tid = threadIdx.x;
    int lane = tid & 31, wrp = tid >> 5;

    // ---- prologue ----
    if (tid < 192) {
        int h = tid >> 6, m = tid & 63;
        int base = (h < 2) ? h * 70 : 140;
        float bias = (h < 2) ? readb[base + m] : writeb[m];
        ksm[h * 64 + m] = tanhf(Psum(b, base + m) + bias);
    } else if (tid >= 320 && tid < 384) {
        int t = tid - 320;
        es[t] = sigf(Psum(b, 210 + t) + writeb[70 + t]);
    } else if (tid >= 384 && tid < 448) {
        int t = tid - 384;
        as_[t] = Psum(b, 274 + t) + writeb[134 + t];
    }
    if (tid < 3) {
        int h = tid;
        int base = (h < 2) ? h * 70 : 140;
        const float* bb = (h < 2) ? (readb + base) : writeb;
        float p64 = Psum(b, base + 64) + bb[64];
        float p65 = Psum(b, base + 65) + bb[65];
        float q0 = Psum(b, base + 66) + bb[66];
        float q1 = Psum(b, base + 67) + bb[67];
        float q2 = Psum(b, base + 68) + bb[68];
        float p69 = Psum(b, base + 69) + bb[69];
        hp[h][0] = softplusf(p64);
        hp[h][1] = sigf(p65);
        float mx = fmaxf(q0, fmaxf(q1, q2));
        float e0 = expf(q0 - mx), e1 = expf(q1 - mx), e2 = expf(q2 - mx);
        float si = 1.0f / (e0 + e1 + e2);
        hp[h][2] = e0 * si; hp[h][3] = e1 * si; hp[h][4] = e2 * si;
        hp[h][5] = 1.0f + softplusf(p69);
    }
    __syncthreads();

    // ---- phase B: stream memory ascending, cosine sims (8 lanes per row) ----
    int q = lane >> 3, s = lane & 7, m0 = s * 8;
    float kreg[3][8];
#pragma unroll
    for (int h = 0; h < 3; h++)
#pragma unroll
        for (int i = 0; i < 8; i++) kreg[h][i] = ksm[h * 64 + m0 + i];
    float kn[3];
#pragma unroll
    for (int h = 0; h < 3; h++) {
        float sq = 0.f;
#pragma unroll
        for (int i = 0; i < 8; i++) sq = fmaf(kreg[h][i], kreg[h][i], sq);
        sq += __shfl_xor_sync(0xffffffffu, sq, 1);
        sq += __shfl_xor_sync(0xffffffffu, sq, 2);
        sq += __shfl_xor_sync(0xffffffffu, sq, 4);
        kn[h] = sqrtf(sq);
    }

    const float* mb = mem + (size_t)b * N_ * M_;
    for (int it = 0; it < 32; it += 2) {
        int na = it * 64 + wrp * 4 + q;
        int nb2 = na + 64;
        float4 va0 = *(const float4*)(mb + na * 64 + m0);
        float4 va1 = *(const float4*)(mb + na * 64 + m0 + 4);
        float4 vb0 = *(const float4*)(mb + nb2 * 64 + m0);
        float4 vb1 = *(const float4*)(mb + nb2 * 64 + m0 + 4);
#pragma unroll
        for (int half = 0; half < 2; half++) {
            float4 v0 = half ? vb0 : va0;
            float4 v1 = half ? vb1 : va1;
            int n = half ? nb2 : na;
            float d0 = 0.f, d1 = 0.f, d2 = 0.f, ss = 0.f;
#pragma unroll
            for (int j = 0; j < 8; j++) {
                float x = (j < 4) ? (&v0.x)[j] : (&v1.x)[j - 4];
                d0 = fmaf(kreg[0][j], x, d0);
                d1 = fmaf(kreg[1][j], x, d1);
                d2 = fmaf(kreg[2][j], x, d2);
                ss = fmaf(x, x, ss);
            }
            d0 += __shfl_xor_sync(0xffffffffu, d0, 1); d0 += __shfl_xor_sync(0xffffffffu, d0, 2); d0 += __shfl_xor_sync(0xffffffffu, d0, 4);
            d1 += __shfl_xor_sync(0xffffffffu, d1, 1); d1 += __shfl_xor_sync(0xffffffffu, d1, 2); d1 += __shfl_xor_sync(0xffffffffu, d1, 4);
            d2 += __shfl_xor_sync(0xffffffffu, d2, 1); d2 += __shfl_xor_sync(0xffffffffu, d2, 2); d2 += __shfl_xor_sync(0xffffffffu, d2, 4);
            ss += __shfl_xor_sync(0xffffffffu, ss, 1); ss += __shfl_xor_sync(0xffffffffu, ss, 2); ss += __shfl_xor_sync(0xffffffffu, ss, 4);
            if (s == 0) {
                float mn = sqrtf(ss);
                sim_s[0 * 2048 + n] = d0 / (kn[0] * mn + EPS_);
                sim_s[1 * 2048 + n] = d1 / (kn[1] * mn + EPS_);
                sim_s[2 * 2048 + n] = d2 / (kn[2] * mn + EPS_);
            }
        }
    }
    __syncthreads();

    // ---- phase C: batched softmax / interpolate / shift / sharpen ----
    // No max-subtraction: z = beta*sim with |beta·sim| small; exp(z)/Σexp(z) is
    // mathematically identical to the max-shifted softmax.
    {
        float z[3][4];
        float ls3[3] = {0.f, 0.f, 0.f};
#pragma unroll
        for (int h = 0; h < 3; h++) {
            float beta = hp[h][0];
#pragma unroll
            for (int j = 0; j < 4; j++) {
                int n = tid + j * 512;
                z[h][j] = __expf(beta * sim_s[h * 2048 + n]);
                ls3[h] += z[h][j];
            }
        }
        blk_red_sum3(ls3, red);
#pragma unroll
        for (int h = 0; h < 3; h++) {
            float g = hp[h][1];
            float invS = 1.0f / ls3[h];
            const float* pwb = prev_ws + ((size_t)h * B_ + b) * N_;
#pragma unroll
            for (int j = 0; j < 4; j++) {
                int n = tid + j * 512;
                z[h][j] = fmaf(g, z[h][j] * invS, (1.0f - g) * __ldcs(&pwb[n]));
            }
        }
#pragma unroll
        for (int h = 0; h < 3; h++)
#pragma unroll
            for (int j = 0; j < 4; j++)
                sim_s[h * 2048 + tid + j * 512] = z[h][j];
        __syncthreads();
        float ps3[3] = {0.f, 0.f, 0.f};
        float wp[3][4];
#pragma unroll
        for (int h = 0; h < 3; h++) {
            float s0 = hp[h][2], s1 = hp[h][3], s2 = hp[h][4], gamma = hp[h][5];
#pragma unroll
            for (int j = 0; j < 4; j++) {
                int n = tid + j * 512;
                float wt = s0 * sim_s[h * 2048 + ((n + 2047) & 2047)]
                         + s1 * sim_s[h * 2048 + n]
                         + s2 * sim_s[h * 2048 + ((n + 1) & 2047)];
                wp[h][j] = exp2f(gamma * __log2f(wt + EPS_));
                ps3[h] += wp[h][j];
            }
        }
        blk_red_sum3(ps3, red);
#pragma unroll
        for (int h = 0; h < 3; h++) {
            float inv2 = 1.0f / (ps3[h] + EPS_);
            float* wout = dout + OFF_W + ((size_t)h * B_ + b) * N_;
#pragma unroll
            for (int j = 0; j < 4; j++) {
                int n = tid + j * 512;
                float wv = wp[h][j] * inv2;
                __stcs(&wout[n], wv);
                sim_s[h * 2048 + n] = wv;
            }
        }
        __syncthreads();
    }

    // ---- phase D: memory write + weighted reads, REVERSE band order ----
    int qd = lane >> 4, md = lane & 15;
    float4 e4 = *(const float4*)&es[md * 4];
    float4 a4 = *(const float4*)&as_[md * 4];
    float racc0[4] = {0.f, 0.f, 0.f, 0.f};
    float racc1[4] = {0.f, 0.f, 0.f, 0.f};
    const float4* msrc = (const float4*)(mem + (size_t)b * N_ * M_);
    float4* mdst = (float4*)(dout + OFF_MEM + (size_t)b * N_ * M_);

    for (int band = 60; band >= 0; band -= 4) {
        float4 v[4]; float w0[4], w1[4], ww[4]; int nn[4];
#pragma unroll
        for (int u = 3; u >= 0; u--) {
            int n = (band + u) * 32 + wrp * 2 + qd;
            nn[u] = n;
            v[u] = __ldcs(&msrc[n * 16 + md]);
            w0[u] = sim_s[n]; w1[u] = sim_s[2048 + n]; ww[u] = sim_s[4096 + n];
        }
#pragma unroll
        for (int u = 3; u >= 0; u--) {
            float4 nv;
            nv.x = fmaf(v[u].x, fmaf(-ww[u], e4.x, 1.0f), ww[u] * a4.x);
            nv.y = fmaf(v[u].y, fmaf(-ww[u], e4.y, 1.0f), ww[u] * a4.y);
            nv.z = fmaf(v[u].z, fmaf(-ww[u], e4.z, 1.0f), ww[u] * a4.z);
            nv.w = fmaf(v[u].w, fmaf(-ww[u], e4.w, 1.0f), ww[u] * a4.w);
            __stcs(&mdst[nn[u] * 16 + md], nv);
            racc0[0] = fmaf(w0[u], v[u].x, racc0[0]);
            racc0[1] = fmaf(w0[u], v[u].y, racc0[1]);
            racc0[2] = fmaf(w0[u], v[u].z, racc0[2]);
            racc0[3] = fmaf(w0[u], v[u].w, racc0[3]);
            racc1[0] = fmaf(w1[u], v[u].x, racc1[0]);
            racc1[1] = fmaf(w1[u], v[u].y, racc1[1]);
            racc1[2] = fmaf(w1[u], v[u].z, racc1[2]);
            racc1[3] = fmaf(w1[u], v[u].w, racc1[3]);
        }
    }
#pragma unroll
    for (int u = 0; u < 4; u++) {
        racc0[u] += __shfl_xor_sync(0xffffffffu, racc0[u], 16);
        racc1[u] += __shfl_xor_sync(0xffffffffu, racc1[u], 16);
    }
    __syncthreads();
    if (lane < 16) {
#pragma unroll
        for (int u = 0; u < 4; u++) {
            wgs[wrp * 128 + md * 4 + u] = racc0[u];
            wgs[wrp * 128 + 64 + md * 4 + u] = racc1[u];
        }
    }
    __syncthreads();
    if (tid < 128) {
        int h = tid >> 6, m = tid & 63;
        float sum = 0.f;
#pragma unroll
        for (int w = 0; w < 16; w++) sum += wgs[w * 128 + h * 64 + m];
        dout[OFF_READS + h * B_ * M_ + b * M_ + m] = sum;
    }
}

// ---------------- K5: output GEMM + sigmoid (2 b per block, 128 blocks) ----------------
__global__ void __launch_bounds__(256) k5_out(const float* __restrict__ outW,
                                              const float* __restrict__ outb,
                                              float* __restrict__ dout) {
    __shared__ float Wst[128][68];
    __shared__ float xs[2][644];
    int tid = threadIdx.x;
    int b0 = blockIdx.x * 2;
    int o = tid & 127, dup = tid >> 7;
    int lr = tid >> 1, c8 = (tid & 1) * 32;

    for (int idx = tid; idx < 2 * 640; idx += 256) {
        int bb = idx / 640, k = idx - bb * 640;
        int b = b0 + bb;
        float v;
        if (k < 512) v = dout[OFF_H + b * 512 + k];
        else if (k < 576) v = dout[OFF_READS + b * 64 + (k - 512)];
        else v = dout[OFF_READS + B_ * M_ + b * 64 + (k - 576)];
        xs[bb][k] = v;
    }

    float acc = 0.f;
    float4 pw[8];
#pragma unroll
    for (int i = 0; i < 8; i++) pw[i] = *(const float4*)(outW + lr * 640 + c8 + 4 * i);
    for (int kt = 0; kt < 10; kt++) {
        __syncthreads();
#pragma unroll
        for (int i = 0; i < 8; i++) *(float4*)&Wst[lr][c8 + 4 * i] = pw[i];
        __syncthreads();
        if (kt + 1 < 10) {
            int kb = (kt + 1) * 64;
#pragma unroll
            for (int i = 0; i < 8; i++) pw[i] = *(const float4*)(outW + lr * 640 + kb + c8 + 4 * i);
        }
        int kb = kt * 64;
#pragma unroll
        for (int k4 = 0; k4 < 16; k4++) {
            float4 wv = *(const float4*)&Wst[o][k4 * 4];
            float4 xv = *(const float4*)&xs[dup][kb + k4 * 4];
            acc = fmaf(wv.x, xv.x, acc);
            acc = fmaf(wv.y, xv.y, acc);
            acc = fmaf(wv.z, xv.z, acc);
            acc = fmaf(wv.w, xv.w, acc);
        }
    }
    dout[OFF_OUT + (b0 + dup) * 128 + o] = sigf(acc + outb[o]);
}

extern "C" void kernel_launch(void* const* d_in, const int* in_sizes, int n_in,
                              void* d_out, int out_size) {
    const float* inp        = (const float*)d_in[0];
    const float* prev_reads = (const float*)d_in[1];
    const float* prev_h     = (const float*)d_in[2];
    const float* prev_c     = (const float*)d_in[3];
    const float* prev_ws    = (const float*)d_in[4];
    const float* memory     = (const float*)d_in[5];
    const float* W_ih       = (const float*)d_in[6];
    const float* W_hh       = (const float*)d_in[7];
    const float* b_lstm     = (const float*)d_in[8];
    const float* read_W     = (const float*)d_in[9];
    const float* read_b     = (const float*)d_in[10];
    const float* write_W    = (const float*)d_in[11];
    const float* write_b    = (const float*)d_in[12];
    const float* out_W      = (const float*)d_in[13];
    const float* out_b      = (const float*)d_in[14];
    float* dout = (float*)d_out;

    k1_gates<<<dim3(16, 4, 4), 256>>>(inp, prev_reads, prev_h, W_ih, W_hh);
    k1b_lstm<<<512, 256>>>(b_lstm, prev_c, dout);
    k2_p<<<dim3(6, 4, 8), 256>>>(read_W, write_W, dout);
    k34_fused<<<256, 512>>>(memory, prev_ws, read_b, write_b, dout);
    k5_out<<<128, 256>>>(out_W, out_b, dout);
}

// round 14
// speedup vs baseline: 1.1463x; 1.0023x over previous
#include <cuda_runtime.h>
#include <math.h>
#include <stdint.h>

#define B_ 256
#define N_ 2048
#define M_ 64
#define H_ 512
#define EPS_ 1e-8f

// d_out float offsets: out, reads, h, c, weights, new_mem
#define OFF_OUT   0
#define OFF_READS 32768
#define OFF_H     65536
#define OFF_C     196608
#define OFF_W     327680
#define OFF_MEM   1900544

__device__ float g_gates4[4 * B_ * 2048];   // split-k partials for gates
__device__ float g_p8[8 * B_ * 352];        // split-k partials for head params

// fast activations: __expf rel-err ~2^-22, far inside the 1e-3 budget
__device__ __forceinline__ float sigf(float x) {
    return __fdividef(1.0f, 1.0f + __expf(-x));
}
__device__ __forceinline__ float tanh_fast(float x) {
    return 2.0f * sigf(2.0f * x) - 1.0f;
}
__device__ __forceinline__ float softplusf(float x) {
    return fmaxf(x, 0.0f) + log1pf(__expf(-fabsf(x)));
}

union U64F2 { unsigned long long u; float2 f; };
__device__ __forceinline__ void ffma2(unsigned long long& d, unsigned long long a, unsigned long long b) {
    asm("fma.rn.f32x2 %0, %1, %2, %0;" : "+l"(d) : "l"(a), "l"(b));
}

// gather a float4 of the concatenated LSTM input x = [inp(128) | r0(64) | r1(64) | h(512)]
__device__ __forceinline__ float4 xcat4(const float* __restrict__ inp,
                                        const float* __restrict__ pr,
                                        const float* __restrict__ ph,
                                        int b, int k) {
    const float* src;
    if (k < 128) src = inp + b * 128 + k;
    else if (k < 192) src = pr + b * 64 + (k - 128);
    else if (k < 256) src = pr + 16384 + b * 64 + (k - 192);
    else src = ph + b * 512 + (k - 256);
    return *(const float4*)src;
}

// ---------------- K1: gates GEMM, k-pair f32x2, split-k=4, fused input gather ----------------
__global__ void __launch_bounds__(256, 2) k1_gates(const float* __restrict__ inp,
                                                   const float* __restrict__ prev_reads,
                                                   const float* __restrict__ prev_h,
                                                   const float* __restrict__ Wih,
                                                   const float* __restrict__ Whh) {
    __shared__ float As[2][64][20];
    __shared__ float Bs[2][128][20];
    int tid = threadIdx.x;
    int j0 = blockIdx.x * 128, b0 = blockIdx.y * 64, ks = blockIdx.z;
    int k_base = ks * 192;
    int tx = tid & 15, ty = tid >> 4;

    int arow = tid >> 2, ak4 = tid & 3;
    int bj0 = tid >> 2, bk4 = tid & 3;

    unsigned long long acc[4][8];
#pragma unroll
    for (int i = 0; i < 4; i++)
#pragma unroll
        for (int j = 0; j < 8; j++) acc[i][j] = 0ull;

    float4 fa, fb0, fb1;
    {
        fa = xcat4(inp, prev_reads, prev_h, b0 + arow, k_base + ak4 * 4);
        int kgb = k_base + bk4 * 4;
        int j1 = j0 + bj0, j2 = j0 + bj0 + 64;
        fb0 = *(const float4*)((kgb < 256) ? (Wih + (size_t)j1 * 256 + kgb) : (Whh + (size_t)j1 * 512 + kgb - 256));
        fb1 = *(const float4*)((kgb < 256) ? (Wih + (size_t)j2 * 256 + kgb) : (Whh + (size_t)j2 * 512 + kgb - 256));
    }
    *(float4*)&As[0][arow][ak4 * 4] = fa;
    *(float4*)&Bs[0][bj0][bk4 * 4] = fb0;
    *(float4*)&Bs[0][bj0 + 64][bk4 * 4] = fb1;
    __syncthreads();

    for (int s = 0; s < 12; s++) {
        int cur = s & 1;
        if (s + 1 < 12) {
            fa = xcat4(inp, prev_reads, prev_h, b0 + arow, k_base + (s + 1) * 16 + ak4 * 4);
            int kgb = k_base + (s + 1) * 16 + bk4 * 4;
            int j1 = j0 + bj0, j2 = j0 + bj0 + 64;
            fb0 = *(const float4*)((kgb < 256) ? (Wih + (size_t)j1 * 256 + kgb) : (Whh + (size_t)j1 * 512 + kgb - 256));
            fb1 = *(const float4*)((kgb < 256) ? (Wih + (size_t)j2 * 256 + kgb) : (Whh + (size_t)j2 * 512 + kgb - 256));
        }
        const float* As_ = &As[cur][0][0];
        const float* Bs_ = &Bs[cur][0][0];
#pragma unroll
        for (int kg = 0; kg < 4; kg++) {
            ulonglong2 au[4];
#pragma unroll
            for (int i = 0; i < 4; i++)
                au[i] = *(const ulonglong2*)(As_ + (ty * 4 + i) * 20 + kg * 4);
#pragma unroll
            for (int jj = 0; jj < 8; jj++) {
                ulonglong2 bu = *(const ulonglong2*)(Bs_ + (tx + 16 * jj) * 20 + kg * 4);
#pragma unroll
                for (int i = 0; i < 4; i++) {
                    ffma2(acc[i][jj], au[i].x, bu.x);
                    ffma2(acc[i][jj], au[i].y, bu.y);
                }
            }
        }
        if (s + 1 < 12) {
            int nxt = (s + 1) & 1;
            *(float4*)&As[nxt][arow][ak4 * 4] = fa;
            *(float4*)&Bs[nxt][bj0][bk4 * 4] = fb0;
            *(float4*)&Bs[nxt][bj0 + 64][bk4 * 4] = fb1;
        }
        __syncthreads();
    }

    float* outp = g_gates4 + (size_t)ks * B_ * 2048;
#pragma unroll
    for (int i = 0; i < 4; i++) {
        int row = (b0 + ty * 4 + i) * 2048 + j0 + tx;
#pragma unroll
        for (int jj = 0; jj < 8; jj++) {
            U64F2 u; u.u = acc[i][jj];
            outp[row + 16 * jj] = u.f.x + u.f.y;
        }
    }
}

// ---------------- K1b: sum partials + LSTM elementwise (float4, fast activations) ----------------
__global__ void k1b_lstm(const float* __restrict__ blstm,
                         const float* __restrict__ prev_c,
                         float* __restrict__ dout) {
    int t = blockIdx.x * 256 + threadIdx.x;   // 32768 threads, 4 h each
    int b = t >> 7;
    int h4 = (t & 127) * 4;
    float4 gi = *(const float4*)(blstm + h4);
    float4 gf = *(const float4*)(blstm + 512 + h4);
    float4 gg = *(const float4*)(blstm + 1024 + h4);
    float4 go = *(const float4*)(blstm + 1536 + h4);
#pragma unroll
    for (int p = 0; p < 4; p++) {
        const float* gr = g_gates4 + (size_t)p * B_ * 2048 + b * 2048;
        float4 a = *(const float4*)(gr + h4);
        float4 bq = *(const float4*)(gr + 512 + h4);
        float4 c4 = *(const float4*)(gr + 1024 + h4);
        float4 d4 = *(const float4*)(gr + 1536 + h4);
        gi.x += a.x;  gi.y += a.y;  gi.z += a.z;  gi.w += a.w;
        gf.x += bq.x; gf.y += bq.y; gf.z += bq.z; gf.w += bq.w;
        gg.x += c4.x; gg.y += c4.y; gg.z += c4.z; gg.w += c4.w;
        go.x += d4.x; go.y += d4.y; go.z += d4.z; go.w += d4.w;
    }
    float4 pc = *(const float4*)(prev_c + b * 512 + h4);
    float4 co, ho;
#pragma unroll
    for (int u = 0; u < 4; u++) {
        float c = sigf((&gf.x)[u]) * (&pc.x)[u] + sigf((&gi.x)[u]) * tanh_fast((&gg.x)[u]);
        (&co.x)[u] = c;
        (&ho.x)[u] = sigf((&go.x)[u]) * tanh_fast(c);
    }
    *(float4*)(dout + OFF_C + b * 512 + h4) = co;
    *(float4*)(dout + OFF_H + b * 512 + h4) = ho;
}

// ---------------- K2: head-param GEMM, 64col x 64b tiles, single k-slab 64, split-k=8 ----------------
__global__ void __launch_bounds__(256) k2_p(const float* __restrict__ readW,
                                            const float* __restrict__ writeW,
                                            const float* __restrict__ dout) {
    __shared__ float Hst[64][68];   // [k][b]
    __shared__ float Wst[64][68];   // [k][col]
    int tid = threadIdx.x;
    int c0 = blockIdx.x * 64, b0 = blockIdx.y * 64, ks = blockIdx.z;
    int kofs = ks * 64;
    int tx = tid & 15, ty = tid >> 4;

    int lrow = tid >> 2, lk16 = (tid & 3) * 16;
    {
        const float* hrow = dout + OFF_H + (b0 + lrow) * 512 + kofs + lk16;
        int col_l = c0 + lrow;
        const float* wrow = 0;
        if (col_l < 140) wrow = readW + (size_t)col_l * 512 + kofs + lk16;
        else if (col_l < 338) wrow = writeW + (size_t)(col_l - 140) * 512 + kofs + lk16;
#pragma unroll
        for (int q = 0; q < 4; q++) {
            float4 hv = *(const float4*)(hrow + 4 * q);
            float4 wv = wrow ? *(const float4*)(wrow + 4 * q) : make_float4(0.f, 0.f, 0.f, 0.f);
#pragma unroll
            for (int c = 0; c < 4; c++) {
                Hst[lk16 + 4 * q + c][lrow] = (&hv.x)[c];
                Wst[lk16 + 4 * q + c][lrow] = (&wv.x)[c];
            }
        }
    }
    __syncthreads();

    float acc[4][4] = {};
#pragma unroll 8
    for (int kk = 0; kk < 64; kk++) {
        float4 h4 = *(const float4*)&Hst[kk][ty * 4];
        float4 w4 = *(const float4*)&Wst[kk][tx * 4];
#pragma unroll
        for (int i = 0; i < 4; i++)
#pragma unroll
            for (int j = 0; j < 4; j++)
                acc[i][j] = fmaf((&h4.x)[i], (&w4.x)[j], acc[i][j]);
    }

    float* outp = g_p8 + (size_t)ks * B_ * 352;
#pragma unroll
    for (int i = 0; i < 4; i++) {
#pragma unroll
        for (int j = 0; j < 4; j++) {
            int col = c0 + tx * 4 + j;
            if (col < 338)
                outp[(size_t)(b0 + ty * 4 + i) * 352 + col] = acc[i][j];
        }
    }
}

// ---------------- packed 3-value block sum reduction (512 threads) ----------------
__device__ __forceinline__ void blk_red_sum3(float v[3], volatile float* red) {
    int lane = threadIdx.x & 31, w = threadIdx.x >> 5;
#pragma unroll
    for (int o = 16; o; o >>= 1) {
        v[0] += __shfl_xor_sync(0xffffffffu, v[0], o);
        v[1] += __shfl_xor_sync(0xffffffffu, v[1], o);
        v[2] += __shfl_xor_sync(0xffffffffu, v[2], o);
    }
    if (lane == 0) { red[w] = v[0]; red[16 + w] = v[1]; red[32 + w] = v[2]; }
    __syncthreads();
    if (w == 0) {
        float x0 = (lane < 16) ? red[lane] : 0.f;
        float x1 = (lane < 16) ? red[16 + lane] : 0.f;
        float x2 = (lane < 16) ? red[32 + lane] : 0.f;
#pragma unroll
        for (int o = 8; o; o >>= 1) {
            x0 += __shfl_xor_sync(0xffffffffu, x0, o);
            x1 += __shfl_xor_sync(0xffffffffu, x1, o);
            x2 += __shfl_xor_sync(0xffffffffu, x2, o);
        }
        if (lane == 0) { red[0] = x0; red[16] = x1; red[32] = x2; }
    }
    __syncthreads();
    v[0] = red[0]; v[1] = red[16]; v[2] = red[32];
    __syncthreads();
}

// sum 8 split-k partials of head params
__device__ __forceinline__ float Psum(int b, int col) {
    float v = 0.f;
#pragma unroll
    for (int p = 0; p < 8; p++)
        v += g_p8[(size_t)p * B_ * 352 + (size_t)b * 352 + col];
    return v;
}

// ---------------- K34: fused addressing + read/write (one block per b, 2/SM) ----------------
__global__ void __launch_bounds__(512, 2) k34_fused(const float* __restrict__ mem,
                                                    const float* __restrict__ prev_ws,
                                                    const float* __restrict__ readb,
                                                    const float* __restrict__ writeb,
                                                    float* __restrict__ dout) {
    __shared__ float sim_s[3 * 2048];
    __shared__ float wgs[2048];
    __shared__ float ksm[3 * 64];
    __shared__ float red[48];
    __shared__ float hp[3][6];
    __shared__ __align__(16) float es[64];
    __shared__ __align__(16) float as_[64];
    int b = blockIdx.x;
    int tid = threadIdx.x;
    int lane = tid & 31, wrp = tid >> 5;

    // ---- prologue ----
    if (tid < 192) {
        int h = tid >> 6, m = tid & 63;
        int base = (h < 2) ? h * 70 : 140;
        float bias = (h < 2) ? readb[base + m] : writeb[m];
        ksm[h * 64 + m] = tanh_fast(Psum(b, base + m) + bias);
    } else if (tid >= 320 && tid < 384) {
        int t = tid - 320;
        es[t] = sigf(Psum(b, 210 + t) + writeb[70 + t]);
    } else if (tid >= 384 && tid < 448) {
        int t = tid - 384;
        as_[t] = Psum(b, 274 + t) + writeb[134 + t];
    }
    if (tid < 3) {
        int h = tid;
        int base = (h < 2) ? h * 70 : 140;
        const float* bb = (h < 2) ? (readb + base) : writeb;
        float p64 = Psum(b, base + 64) + bb[64];
        float p65 = Psum(b, base + 65) + bb[65];
        float q0 = Psum(b, base + 66) + bb[66];
        float q1 = Psum(b, base + 67) + bb[67];
        float q2 = Psum(b, base + 68) + bb[68];
        float p69 = Psum(b, base + 69) + bb[69];
        hp[h][0] = softplusf(p64);
        hp[h][1] = sigf(p65);
        float mx = fmaxf(q0, fmaxf(q1, q2));
        float e0 = __expf(q0 - mx), e1 = __expf(q1 - mx), e2 = __expf(q2 - mx);
        float si = __fdividef(1.0f, e0 + e1 + e2);
        hp[h][2] = e0 * si; hp[h][3] = e1 * si; hp[h][4] = e2 * si;
        hp[h][5] = 1.0f + softplusf(p69);
    }
    __syncthreads();

    // ---- phase B: stream memory ascending, cosine sims (8 lanes per row) ----
    int q = lane >> 3, s = lane & 7, m0 = s * 8;
    float kreg[3][8];
#pragma unroll
    for (int h = 0; h < 3; h++)
#pragma unroll
        for (int i = 0; i < 8; i++) kreg[h][i] = ksm[h * 64 + m0 + i];
    float kn[3];
#pragma unroll
    for (int h = 0; h < 3; h++) {
        float sq = 0.f;
#pragma unroll
        for (int i = 0; i < 8; i++) sq = fmaf(kreg[h][i], kreg[h][i], sq);
        sq += __shfl_xor_sync(0xffffffffu, sq, 1);
        sq += __shfl_xor_sync(0xffffffffu, sq, 2);
        sq += __shfl_xor_sync(0xffffffffu, sq, 4);
        kn[h] = sqrtf(sq);
    }

    const float* mb = mem + (size_t)b * N_ * M_;
    for (int it = 0; it < 32; it += 2) {
        int na = it * 64 + wrp * 4 + q;
        int nb2 = na + 64;
        float4 va0 = *(const float4*)(mb + na * 64 + m0);
        float4 va1 = *(const float4*)(mb + na * 64 + m0 + 4);
        float4 vb0 = *(const float4*)(mb + nb2 * 64 + m0);
        float4 vb1 = *(const float4*)(mb + nb2 * 64 + m0 + 4);
#pragma unroll
        for (int half = 0; half < 2; half++) {
            float4 v0 = half ? vb0 : va0;
            float4 v1 = half ? vb1 : va1;
            int n = half ? nb2 : na;
            float d0 = 0.f, d1 = 0.f, d2 = 0.f, ss = 0.f;
#pragma unroll
            for (int j = 0; j < 8; j++) {
                float x = (j < 4) ? (&v0.x)[j] : (&v1.x)[j - 4];
                d0 = fmaf(kreg[0][j], x, d0);
                d1 = fmaf(kreg[1][j], x, d1);
                d2 = fmaf(kreg[2][j], x, d2);
                ss = fmaf(x, x, ss);
            }
            d0 += __shfl_xor_sync(0xffffffffu, d0, 1); d0 += __shfl_xor_sync(0xffffffffu, d0, 2); d0 += __shfl_xor_sync(0xffffffffu, d0, 4);
            d1 += __shfl_xor_sync(0xffffffffu, d1, 1); d1 += __shfl_xor_sync(0xffffffffu, d1, 2); d1 += __shfl_xor_sync(0xffffffffu, d1, 4);
            d2 += __shfl_xor_sync(0xffffffffu, d2, 1); d2 += __shfl_xor_sync(0xffffffffu, d2, 2); d2 += __shfl_xor_sync(0xffffffffu, d2, 4);
            ss += __shfl_xor_sync(0xffffffffu, ss, 1); ss += __shfl_xor_sync(0xffffffffu, ss, 2); ss += __shfl_xor_sync(0xffffffffu, ss, 4);
            if (s == 0) {
                float mn = sqrtf(ss);
                sim_s[0 * 2048 + n] = d0 / (kn[0] * mn + EPS_);
                sim_s[1 * 2048 + n] = d1 / (kn[1] * mn + EPS_);
                sim_s[2 * 2048 + n] = d2 / (kn[2] * mn + EPS_);
            }
        }
    }
    __syncthreads();

    // ---- phase C: batched softmax (no max shift) / interpolate / shift / sharpen ----
    {
        float z[3][4];
        float ls3[3] = {0.f, 0.f, 0.f};
#pragma unroll
        for (int h = 0; h < 3; h++) {
            float beta = hp[h][0];
#pragma unroll
            for (int j = 0; j < 4; j++) {
                int n = tid + j * 512;
                z[h][j] = __expf(beta * sim_s[h * 2048 + n]);
                ls3[h] += z[h][j];
            }
        }
        blk_red_sum3(ls3, red);
#pragma unroll
        for (int h = 0; h < 3; h++) {
            float g = hp[h][1];
            float invS = 1.0f / ls3[h];
            const float* pwb = prev_ws + ((size_t)h * B_ + b) * N_;
#pragma unroll
            for (int j = 0; j < 4; j++) {
                int n = tid + j * 512;
                z[h][j] = fmaf(g, z[h][j] * invS, (1.0f - g) * __ldcs(&pwb[n]));
            }
        }
#pragma unroll
        for (int h = 0; h < 3; h++)
#pragma unroll
            for (int j = 0; j < 4; j++)
                sim_s[h * 2048 + tid + j * 512] = z[h][j];
        __syncthreads();
        float ps3[3] = {0.f, 0.f, 0.f};
        float wp[3][4];
#pragma unroll
        for (int h = 0; h < 3; h++) {
            float s0 = hp[h][2], s1 = hp[h][3], s2 = hp[h][4], gamma = hp[h][5];
#pragma unroll
            for (int j = 0; j < 4; j++) {
                int n = tid + j * 512;
                float wt = s0 * sim_s[h * 2048 + ((n + 2047) & 2047)]
                         + s1 * sim_s[h * 2048 + n]
                         + s2 * sim_s[h * 2048 + ((n + 1) & 2047)];
                wp[h][j] = exp2f(gamma * __log2f(wt + EPS_));
                ps3[h] += wp[h][j];
            }
        }
        blk_red_sum3(ps3, red);
#pragma unroll
        for (int h = 0; h < 3; h++) {
            float inv2 = 1.0f / (ps3[h] + EPS_);
            float* wout = dout + OFF_W + ((size_t)h * B_ + b) * N_;
#pragma unroll
            for (int j = 0; j < 4; j++) {
                int n = tid + j * 512;
                float wv = wp[h][j] * inv2;
                __stcs(&wout[n], wv);
                sim_s[h * 2048 + n] = wv;
            }
        }
        __syncthreads();
    }

    // ---- phase D: memory write + weighted reads, REVERSE band order ----
    int qd = lane >> 4, md = lane & 15;
    float4 e4 = *(const float4*)&es[md * 4];
    float4 a4 = *(const float4*)&as_[md * 4];
    float racc0[4] = {0.f, 0.f, 0.f, 0.f};
    float racc1[4] = {0.f, 0.f, 0.f, 0.f};
    const float4* msrc = (const float4*)(mem + (size_t)b * N_ * M_);
    float4* mdst = (float4*)(dout + OFF_MEM + (size_t)b * N_ * M_);

    for (int band = 60; band >= 0; band -= 4) {
        float4 v[4]; float w0[4], w1[4], ww[4]; int nn[4];
#pragma unroll
        for (int u = 3; u >= 0; u--) {
            int n = (band + u) * 32 + wrp * 2 + qd;
            nn[u] = n;
            v[u] = __ldcs(&msrc[n * 16 + md]);
            w0[u] = sim_s[n]; w1[u] = sim_s[2048 + n]; ww[u] = sim_s[4096 + n];
        }
#pragma unroll
        for (int u = 3; u >= 0; u--) {
            float4 nv;
            nv.x = fmaf(v[u].x, fmaf(-ww[u], e4.x, 1.0f), ww[u] * a4.x);
            nv.y = fmaf(v[u].y, fmaf(-ww[u], e4.y, 1.0f), ww[u] * a4.y);
            nv.z = fmaf(v[u].z, fmaf(-ww[u], e4.z, 1.0f), ww[u] * a4.z);
            nv.w = fmaf(v[u].w, fmaf(-ww[u], e4.w, 1.0f), ww[u] * a4.w);
            __stcs(&mdst[nn[u] * 16 + md], nv);
            racc0[0] = fmaf(w0[u], v[u].x, racc0[0]);
            racc0[1] = fmaf(w0[u], v[u].y, racc0[1]);
            racc0[2] = fmaf(w0[u], v[u].z, racc0[2]);
            racc0[3] = fmaf(w0[u], v[u].w, racc0[3]);
            racc1[0] = fmaf(w1[u], v[u].x, racc1[0]);
            racc1[1] = fmaf(w1[u], v[u].y, racc1[1]);
            racc1[2] = fmaf(w1[u], v[u].z, racc1[2]);
            racc1[3] = fmaf(w1[u], v[u].w, racc1[3]);
        }
    }
#pragma unroll
    for (int u = 0; u < 4; u++) {
        racc0[u] += __shfl_xor_sync(0xffffffffu, racc0[u], 16);
        racc1[u] += __shfl_xor_sync(0xffffffffu, racc1[u], 16);
    }
    __syncthreads();
    if (lane < 16) {
#pragma unroll
        for (int u = 0; u < 4; u++) {
            wgs[wrp * 128 + md * 4 + u] = racc0[u];
            wgs[wrp * 128 + 64 + md * 4 + u] = racc1[u];
        }
    }
    __syncthreads();
    if (tid < 128) {
        int h = tid >> 6, m = tid & 63;
        float sum = 0.f;
#pragma unroll
        for (int w = 0; w < 16; w++) sum += wgs[w * 128 + h * 64 + m];
        dout[OFF_READS + h * B_ * M_ + b * M_ + m] = sum;
    }
}

// ---------------- K5: output GEMM + sigmoid (2 b per block, f32x2 inner) ----------------
__global__ void __launch_bounds__(256) k5_out(const float* __restrict__ outW,
                                              const float* __restrict__ outb,
                                              float* __restrict__ dout) {
    __shared__ float Wst[128][68];
    __shared__ float xs[2][644];
    int tid = threadIdx.x;
    int b0 = blockIdx.x * 2;
    int o = tid & 127, dup = tid >> 7;
    int lr = tid >> 1, c8 = (tid & 1) * 32;

    for (int idx = tid; idx < 2 * 640; idx += 256) {
        int bb = idx / 640, k = idx - bb * 640;
        int b = b0 + bb;
        float v;
        if (k < 512) v = dout[OFF_H + b * 512 + k];
        else if (k < 576) v = dout[OFF_READS + b * 64 + (k - 512)];
        else v = dout[OFF_READS + B_ * M_ + b * 64 + (k - 576)];
        xs[bb][k] = v;
    }

    unsigned long long acc = 0ull;
    float4 pw[8];
#pragma unroll
    for (int i = 0; i < 8; i++) pw[i] = *(const float4*)(outW + lr * 640 + c8 + 4 * i);
    for (int kt = 0; kt < 10; kt++) {
        __syncthreads();
#pragma unroll
        for (int i = 0; i < 8; i++) *(float4*)&Wst[lr][c8 + 4 * i] = pw[i];
        __syncthreads();
        if (kt + 1 < 10) {
            int kb = (kt + 1) * 64;
#pragma unroll
            for (int i = 0; i < 8; i++) pw[i] = *(const float4*)(outW + lr * 640 + kb + c8 + 4 * i);
        }
        int kb = kt * 64;
#pragma unroll
        for (int k4 = 0; k4 < 16; k4++) {
            ulonglong2 wv = *(const ulonglong2*)&Wst[o][k4 * 4];
            ulonglong2 xv = *(const ulonglong2*)&xs[dup][kb + k4 * 4];
            ffma2(acc, wv.x, xv.x);
            ffma2(acc, wv.y, xv.y);
        }
    }
    U64F2 u; u.u = acc;
    dout[OFF_OUT + (b0 + dup) * 128 + o] = sigf(u.f.x + u.f.y + outb[o]);
}

extern "C" void kernel_launch(void* const* d_in, const int* in_sizes, int n_in,
                              void* d_out, int out_size) {
    const float* inp        = (const float*)d_in[0];
    const float* prev_reads = (const float*)d_in[1];
    const float* prev_h     = (const float*)d_in[2];
    const float* prev_c     = (const float*)d_in[3];
    const float* prev_ws    = (const float*)d_in[4];
    const float* memory     = (const float*)d_in[5];
    const float* W_ih       = (const float*)d_in[6];
    const float* W_hh       = (const float*)d_in[7];
    const float* b_lstm     = (const float*)d_in[8];
    const float* read_W     = (const float*)d_in[9];
    const float* read_b     = (const float*)d_in[10];
    const float* write_W    = (const float*)d_in[11];
    const float* write_b    = (const float*)d_in[12];
    const float* out_W      = (const float*)d_in[13];
    const float* out_b      = (const float*)d_in[14];
    float* dout = (float*)d_out;

    k1_gates<<<dim3(16, 4, 4), 256>>>(inp, prev_reads, prev_h, W_ih, W_hh);
    k1b_lstm<<<128, 256>>>(b_lstm, prev_c, dout);
    k2_p<<<dim3(6, 4, 8), 256>>>(read_W, write_W, dout);
    k34_fused<<<256, 512>>>(memory, prev_ws, read_b, write_b, dout);
    k5_out<<<128, 256>>>(out_W, out_b, dout);
}

// round 15
// speedup vs baseline: 1.2760x; 1.1131x over previous
#include <cuda_runtime.h>
#include <math.h>
#include <stdint.h>

#define B_ 256
#define N_ 2048
#define M_ 64
#define H_ 512
#define EPS_ 1e-8f

// d_out float offsets: out, reads, h, c, weights, new_mem
#define OFF_OUT   0
#define OFF_READS 32768
#define OFF_H     65536
#define OFF_C     196608
#define OFF_W     327680
#define OFF_MEM   1900544

__device__ float g_gates4[4 * B_ * 2048];   // split-k partials for gates
__device__ float g_p8[8 * B_ * 352];        // split-k partials for head params

// fast activations: __expf rel-err ~2^-22, far inside the 1e-3 budget
__device__ __forceinline__ float sigf(float x) {
    return __fdividef(1.0f, 1.0f + __expf(-x));
}
__device__ __forceinline__ float tanh_fast(float x) {
    return 2.0f * sigf(2.0f * x) - 1.0f;
}
__device__ __forceinline__ float softplusf(float x) {
    return fmaxf(x, 0.0f) + log1pf(__expf(-fabsf(x)));
}

union U64F2 { unsigned long long u; float2 f; };
__device__ __forceinline__ void ffma2(unsigned long long& d, unsigned long long a, unsigned long long b) {
    asm("fma.rn.f32x2 %0, %1, %2, %0;" : "+l"(d) : "l"(a), "l"(b));
}

// gather a float4 of the concatenated LSTM input x = [inp(128) | r0(64) | r1(64) | h(512)]
__device__ __forceinline__ float4 xcat4(const float* __restrict__ inp,
                                        const float* __restrict__ pr,
                                        const float* __restrict__ ph,
                                        int b, int k) {
    const float* src;
    if (k < 128) src = inp + b * 128 + k;
    else if (k < 192) src = pr + b * 64 + (k - 128);
    else if (k < 256) src = pr + 16384 + b * 64 + (k - 192);
    else src = ph + b * 512 + (k - 256);
    return *(const float4*)src;
}

// ---------------- K1: gates GEMM, k-pair f32x2, split-k=4, fused input gather ----------------
__global__ void __launch_bounds__(256, 2) k1_gates(const float* __restrict__ inp,
                                                   const float* __restrict__ prev_reads,
                                                   const float* __restrict__ prev_h,
                                                   const float* __restrict__ Wih,
                                                   const float* __restrict__ Whh) {
    __shared__ float As[2][64][20];
    __shared__ float Bs[2][128][20];
    int tid = threadIdx.x;
    int j0 = blockIdx.x * 128, b0 = blockIdx.y * 64, ks = blockIdx.z;
    int k_base = ks * 192;
    int tx = tid & 15, ty = tid >> 4;

    int arow = tid >> 2, ak4 = tid & 3;
    int bj0 = tid >> 2, bk4 = tid & 3;

    unsigned long long acc[4][8];
#pragma unroll
    for (int i = 0; i < 4; i++)
#pragma unroll
        for (int j = 0; j < 8; j++) acc[i][j] = 0ull;

    float4 fa, fb0, fb1;
    {
        fa = xcat4(inp, prev_reads, prev_h, b0 + arow, k_base + ak4 * 4);
        int kgb = k_base + bk4 * 4;
        int j1 = j0 + bj0, j2 = j0 + bj0 + 64;
        fb0 = *(const float4*)((kgb < 256) ? (Wih + (size_t)j1 * 256 + kgb) : (Whh + (size_t)j1 * 512 + kgb - 256));
        fb1 = *(const float4*)((kgb < 256) ? (Wih + (size_t)j2 * 256 + kgb) : (Whh + (size_t)j2 * 512 + kgb - 256));
    }
    *(float4*)&As[0][arow][ak4 * 4] = fa;
    *(float4*)&Bs[0][bj0][bk4 * 4] = fb0;
    *(float4*)&Bs[0][bj0 + 64][bk4 * 4] = fb1;
    __syncthreads();

    for (int s = 0; s < 12; s++) {
        int cur = s & 1;
        if (s + 1 < 12) {
            fa = xcat4(inp, prev_reads, prev_h, b0 + arow, k_base + (s + 1) * 16 + ak4 * 4);
            int kgb = k_base + (s + 1) * 16 + bk4 * 4;
            int j1 = j0 + bj0, j2 = j0 + bj0 + 64;
            fb0 = *(const float4*)((kgb < 256) ? (Wih + (size_t)j1 * 256 + kgb) : (Whh + (size_t)j1 * 512 + kgb - 256));
            fb1 = *(const float4*)((kgb < 256) ? (Wih + (size_t)j2 * 256 + kgb) : (Whh + (size_t)j2 * 512 + kgb - 256));
        }
        const float* As_ = &As[cur][0][0];
        const float* Bs_ = &Bs[cur][0][0];
#pragma unroll
        for (int kg = 0; kg < 4; kg++) {
            ulonglong2 au[4];
#pragma unroll
            for (int i = 0; i < 4; i++)
                au[i] = *(const ulonglong2*)(As_ + (ty * 4 + i) * 20 + kg * 4);
#pragma unroll
            for (int jj = 0; jj < 8; jj++) {
                ulonglong2 bu = *(const ulonglong2*)(Bs_ + (tx + 16 * jj) * 20 + kg * 4);
#pragma unroll
                for (int i = 0; i < 4; i++) {
                    ffma2(acc[i][jj], au[i].x, bu.x);
                    ffma2(acc[i][jj], au[i].y, bu.y);
                }
            }
        }
        if (s + 1 < 12) {
            int nxt = (s + 1) & 1;
            *(float4*)&As[nxt][arow][ak4 * 4] = fa;
            *(float4*)&Bs[nxt][bj0][bk4 * 4] = fb0;
            *(float4*)&Bs[nxt][bj0 + 64][bk4 * 4] = fb1;
        }
        __syncthreads();
    }

    float* outp = g_gates4 + (size_t)ks * B_ * 2048;
#pragma unroll
    for (int i = 0; i < 4; i++) {
        int row = (b0 + ty * 4 + i) * 2048 + j0 + tx;
#pragma unroll
        for (int jj = 0; jj < 8; jj++) {
            U64F2 u; u.u = acc[i][jj];
            outp[row + 16 * jj] = u.f.x + u.f.y;
        }
    }
}

// ---------------- K1b: sum partials + LSTM elementwise (float4, fast activations) ----------------
__global__ void k1b_lstm(const float* __restrict__ blstm,
                         const float* __restrict__ prev_c,
                         float* __restrict__ dout) {
    int t = blockIdx.x * 256 + threadIdx.x;   // 32768 threads, 4 h each
    int b = t >> 7;
    int h4 = (t & 127) * 4;
    float4 gi = *(const float4*)(blstm + h4);
    float4 gf = *(const float4*)(blstm + 512 + h4);
    float4 gg = *(const float4*)(blstm + 1024 + h4);
    float4 go = *(const float4*)(blstm + 1536 + h4);
#pragma unroll
    for (int p = 0; p < 4; p++) {
        const float* gr = g_gates4 + (size_t)p * B_ * 2048 + b * 2048;
        float4 a = *(const float4*)(gr + h4);
        float4 bq = *(const float4*)(gr + 512 + h4);
        float4 c4 = *(const float4*)(gr + 1024 + h4);
        float4 d4 = *(const float4*)(gr + 1536 + h4);
        gi.x += a.x;  gi.y += a.y;  gi.z += a.z;  gi.w += a.w;
        gf.x += bq.x; gf.y += bq.y; gf.z += bq.z; gf.w += bq.w;
        gg.x += c4.x; gg.y += c4.y; gg.z += c4.z; gg.w += c4.w;
        go.x += d4.x; go.y += d4.y; go.z += d4.z; go.w += d4.w;
    }
    float4 pc = *(const float4*)(prev_c + b * 512 + h4);
    float4 co, ho;
#pragma unroll
    for (int u = 0; u < 4; u++) {
        float c = sigf((&gf.x)[u]) * (&pc.x)[u] + sigf((&gi.x)[u]) * tanh_fast((&gg.x)[u]);
        (&co.x)[u] = c;
        (&ho.x)[u] = sigf((&go.x)[u]) * tanh_fast(c);
    }
    *(float4*)(dout + OFF_C + b * 512 + h4) = co;
    *(float4*)(dout + OFF_H + b * 512 + h4) = ho;
}

// ---------------- K2: head-param GEMM, 64col x 64b tiles, single k-slab 64, split-k=8 ----------------
__global__ void __launch_bounds__(256) k2_p(const float* __restrict__ readW,
                                            const float* __restrict__ writeW,
                                            const float* __restrict__ dout) {
    __shared__ float Hst[64][68];   // [k][b]
    __shared__ float Wst[64][68];   // [k][col]
    int tid = threadIdx.x;
    int c0 = blockIdx.x * 64, b0 = blockIdx.y * 64, ks = blockIdx.z;
    int kofs = ks * 64;
    int tx = tid & 15, ty = tid >> 4;

    int lrow = tid >> 2, lk16 = (tid & 3) * 16;
    {
        const float* hrow = dout + OFF_H + (b0 + lrow) * 512 + kofs + lk16;
        int col_l = c0 + lrow;
        const float* wrow = 0;
        if (col_l < 140) wrow = readW + (size_t)col_l * 512 + kofs + lk16;
        else if (col_l < 338) wrow = writeW + (size_t)(col_l - 140) * 512 + kofs + lk16;
#pragma unroll
        for (int q = 0; q < 4; q++) {
            float4 hv = *(const float4*)(hrow + 4 * q);
            float4 wv = wrow ? *(const float4*)(wrow + 4 * q) : make_float4(0.f, 0.f, 0.f, 0.f);
#pragma unroll
            for (int c = 0; c < 4; c++) {
                Hst[lk16 + 4 * q + c][lrow] = (&hv.x)[c];
                Wst[lk16 + 4 * q + c][lrow] = (&wv.x)[c];
            }
        }
    }
    __syncthreads();

    float acc[4][4] = {};
#pragma unroll 8
    for (int kk = 0; kk < 64; kk++) {
        float4 h4 = *(const float4*)&Hst[kk][ty * 4];
        float4 w4 = *(const float4*)&Wst[kk][tx * 4];
#pragma unroll
        for (int i = 0; i < 4; i++)
#pragma unroll
            for (int j = 0; j < 4; j++)
                acc[i][j] = fmaf((&h4.x)[i], (&w4.x)[j], acc[i][j]);
    }

    float* outp = g_p8 + (size_t)ks * B_ * 352;
#pragma unroll
    for (int i = 0; i < 4; i++) {
#pragma unroll
        for (int j = 0; j < 4; j++) {
            int col = c0 + tx * 4 + j;
            if (col < 338)
                outp[(size_t)(b0 + ty * 4 + i) * 352 + col] = acc[i][j];
        }
    }
}

// ---------------- packed 3-value block sum reduction (512 threads) ----------------
__device__ __forceinline__ void blk_red_sum3(float v[3], volatile float* red) {
    int lane = threadIdx.x & 31, w = threadIdx.x >> 5;
#pragma unroll
    for (int o = 16; o; o >>= 1) {
        v[0] += __shfl_xor_sync(0xffffffffu, v[0], o);
        v[1] += __shfl_xor_sync(0xffffffffu, v[1], o);
        v[2] += __shfl_xor_sync(0xffffffffu, v[2], o);
    }
    if (lane == 0) { red[w] = v[0]; red[16 + w] = v[1]; red[32 + w] = v[2]; }
    __syncthreads();
    if (w == 0) {
        float x0 = (lane < 16) ? red[lane] : 0.f;
        float x1 = (lane < 16) ? red[16 + lane] : 0.f;
        float x2 = (lane < 16) ? red[32 + lane] : 0.f;
#pragma unroll
        for (int o = 8; o; o >>= 1) {
            x0 += __shfl_xor_sync(0xffffffffu, x0, o);
            x1 += __shfl_xor_sync(0xffffffffu, x1, o);
            x2 += __shfl_xor_sync(0xffffffffu, x2, o);
        }
        if (lane == 0) { red[0] = x0; red[16] = x1; red[32] = x2; }
    }
    __syncthreads();
    v[0] = red[0]; v[1] = red[16]; v[2] = red[32];
    __syncthreads();
}

// sum 8 split-k partials of head params
__device__ __forceinline__ float Psum(int b, int col) {
    float v = 0.f;
#pragma unroll
    for (int p = 0; p < 8; p++)
        v += g_p8[(size_t)p * B_ * 352 + (size_t)b * 352 + col];
    return v;
}

// ---------------- K345: fused addressing + read/write + output GEMM (one block per b, 2/SM) ----------------
__global__ void __launch_bounds__(512, 2) k345_fused(const float* __restrict__ mem,
                                                     const float* __restrict__ prev_ws,
                                                     const float* __restrict__ readb,
                                                     const float* __restrict__ writeb,
                                                     const float* __restrict__ outW,
                                                     const float* __restrict__ outb,
                                                     float* __restrict__ dout) {
    __shared__ float sim_s[3 * 2048];
    __shared__ float wgs[2048];
    __shared__ float ksm[3 * 64];
    __shared__ float red[48];
    __shared__ float hp[3][6];
    __shared__ __align__(16) float es[64];
    __shared__ __align__(16) float as_[64];
    int b = blockIdx.x;
    int tid = threadIdx.x;
    int lane = tid & 31, wrp = tid >> 5;

    // ---- prologue ----
    if (tid < 192) {
        int h = tid >> 6, m = tid & 63;
        int base = (h < 2) ? h * 70 : 140;
        float bias = (h < 2) ? readb[base + m] : writeb[m];
        ksm[h * 64 + m] = tanh_fast(Psum(b, base + m) + bias);
    } else if (tid >= 320 && tid < 384) {
        int t = tid - 320;
        es[t] = sigf(Psum(b, 210 + t) + writeb[70 + t]);
    } else if (tid >= 384 && tid < 448) {
        int t = tid - 384;
        as_[t] = Psum(b, 274 + t) + writeb[134 + t];
    }
    if (tid < 3) {
        int h = tid;
        int base = (h < 2) ? h * 70 : 140;
        const float* bb = (h < 2) ? (readb + base) : writeb;
        float p64 = Psum(b, base + 64) + bb[64];
        float p65 = Psum(b, base + 65) + bb[65];
        float q0 = Psum(b, base + 66) + bb[66];
        float q1 = Psum(b, base + 67) + bb[67];
        float q2 = Psum(b, base + 68) + bb[68];
        float p69 = Psum(b, base + 69) + bb[69];
        hp[h][0] = softplusf(p64);
        hp[h][1] = sigf(p65);
        float mx = fmaxf(q0, fmaxf(q1, q2));
        float e0 = __expf(q0 - mx), e1 = __expf(q1 - mx), e2 = __expf(q2 - mx);
        float si = __fdividef(1.0f, e0 + e1 + e2);
        hp[h][2] = e0 * si; hp[h][3] = e1 * si; hp[h][4] = e2 * si;
        hp[h][5] = 1.0f + softplusf(p69);
    }
    __syncthreads();

    // ---- phase B: stream memory ascending, cosine sims (8 lanes per row) ----
    int q = lane >> 3, s = lane & 7, m0 = s * 8;
    float kreg[3][8];
#pragma unroll
    for (int h = 0; h < 3; h++)
#pragma unroll
        for (int i = 0; i < 8; i++) kreg[h][i] = ksm[h * 64 + m0 + i];
    float kn[3];
#pragma unroll
    for (int h = 0; h < 3; h++) {
        float sq = 0.f;
#pragma unroll
        for (int i = 0; i < 8; i++) sq = fmaf(kreg[h][i], kreg[h][i], sq);
        sq += __shfl_xor_sync(0xffffffffu, sq, 1);
        sq += __shfl_xor_sync(0xffffffffu, sq, 2);
        sq += __shfl_xor_sync(0xffffffffu, sq, 4);
        kn[h] = sqrtf(sq);
    }

    const float* mb = mem + (size_t)b * N_ * M_;
    for (int it = 0; it < 32; it += 2) {
        int na = it * 64 + wrp * 4 + q;
        int nb2 = na + 64;
        float4 va0 = *(const float4*)(mb + na * 64 + m0);
        float4 va1 = *(const float4*)(mb + na * 64 + m0 + 4);
        float4 vb0 = *(const float4*)(mb + nb2 * 64 + m0);
        float4 vb1 = *(const float4*)(mb + nb2 * 64 + m0 + 4);
#pragma unroll
        for (int half = 0; half < 2; half++) {
            float4 v0 = half ? vb0 : va0;
            float4 v1 = half ? vb1 : va1;
            int n = half ? nb2 : na;
            float d0 = 0.f, d1 = 0.f, d2 = 0.f, ss = 0.f;
#pragma unroll
            for (int j = 0; j < 8; j++) {
                float x = (j < 4) ? (&v0.x)[j] : (&v1.x)[j - 4];
                d0 = fmaf(kreg[0][j], x, d0);
                d1 = fmaf(kreg[1][j], x, d1);
                d2 = fmaf(kreg[2][j], x, d2);
                ss = fmaf(x, x, ss);
            }
            d0 += __shfl_xor_sync(0xffffffffu, d0, 1); d0 += __shfl_xor_sync(0xffffffffu, d0, 2); d0 += __shfl_xor_sync(0xffffffffu, d0, 4);
            d1 += __shfl_xor_sync(0xffffffffu, d1, 1); d1 += __shfl_xor_sync(0xffffffffu, d1, 2); d1 += __shfl_xor_sync(0xffffffffu, d1, 4);
            d2 += __shfl_xor_sync(0xffffffffu, d2, 1); d2 += __shfl_xor_sync(0xffffffffu, d2, 2); d2 += __shfl_xor_sync(0xffffffffu, d2, 4);
            ss += __shfl_xor_sync(0xffffffffu, ss, 1); ss += __shfl_xor_sync(0xffffffffu, ss, 2); ss += __shfl_xor_sync(0xffffffffu, ss, 4);
            if (s == 0) {
                float mn = sqrtf(ss);
                sim_s[0 * 2048 + n] = d0 / (kn[0] * mn + EPS_);
                sim_s[1 * 2048 + n] = d1 / (kn[1] * mn + EPS_);
                sim_s[2 * 2048 + n] = d2 / (kn[2] * mn + EPS_);
            }
        }
    }
    __syncthreads();

    // ---- phase C: batched softmax (no max shift) / interpolate / shift / sharpen ----
    {
        float z[3][4];
        float ls3[3] = {0.f, 0.f, 0.f};
#pragma unroll
        for (int h = 0; h < 3; h++) {
            float beta = hp[h][0];
#pragma unroll
            for (int j = 0; j < 4; j++) {
                int n = tid + j * 512;
                z[h][j] = __expf(beta * sim_s[h * 2048 + n]);
                ls3[h] += z[h][j];
            }
        }
        blk_red_sum3(ls3, red);
#pragma unroll
        for (int h = 0; h < 3; h++) {
            float g = hp[h][1];
            float invS = 1.0f / ls3[h];
            const float* pwb = prev_ws + ((size_t)h * B_ + b) * N_;
#pragma unroll
            for (int j = 0; j < 4; j++) {
                int n = tid + j * 512;
                z[h][j] = fmaf(g, z[h][j] * invS, (1.0f - g) * __ldcs(&pwb[n]));
            }
        }
#pragma unroll
        for (int h = 0; h < 3; h++)
#pragma unroll
            for (int j = 0; j < 4; j++)
                sim_s[h * 2048 + tid + j * 512] = z[h][j];
        __syncthreads();
        float ps3[3] = {0.f, 0.f, 0.f};
        float wp[3][4];
#pragma unroll
        for (int h = 0; h < 3; h++) {
            float s0 = hp[h][2], s1 = hp[h][3], s2 = hp[h][4], gamma = hp[h][5];
#pragma unroll
            for (int j = 0; j < 4; j++) {
                int n = tid + j * 512;
                float wt = s0 * sim_s[h * 2048 + ((n + 2047) & 2047)]
                         + s1 * sim_s[h * 2048 + n]
                         + s2 * sim_s[h * 2048 + ((n + 1) & 2047)];
                wp[h][j] = exp2f(gamma * __log2f(wt + EPS_));
                ps3[h] += wp[h][j];
            }
        }
        blk_red_sum3(ps3, red);
#pragma unroll
        for (int h = 0; h < 3; h++) {
            float inv2 = 1.0f / (ps3[h] + EPS_);
            float* wout = dout + OFF_W + ((size_t)h * B_ + b) * N_;
#pragma unroll
            for (int j = 0; j < 4; j++) {
                int n = tid + j * 512;
                float wv = wp[h][j] * inv2;
                __stcs(&wout[n], wv);
                sim_s[h * 2048 + n] = wv;
            }
        }
        __syncthreads();
    }

    // ---- phase D: memory write + weighted reads, REVERSE band order ----
    int qd = lane >> 4, md = lane & 15;
    float4 e4 = *(const float4*)&es[md * 4];
    float4 a4 = *(const float4*)&as_[md * 4];
    float racc0[4] = {0.f, 0.f, 0.f, 0.f};
    float racc1[4] = {0.f, 0.f, 0.f, 0.f};
    const float4* msrc = (const float4*)(mem + (size_t)b * N_ * M_);
    float4* mdst = (float4*)(dout + OFF_MEM + (size_t)b * N_ * M_);

    for (int band = 60; band >= 0; band -= 4) {
        float4 v[4]; float w0[4], w1[4], ww[4]; int nn[4];
#pragma unroll
        for (int u = 3; u >= 0; u--) {
            int n = (band + u) * 32 + wrp * 2 + qd;
            nn[u] = n;
            v[u] = __ldcs(&msrc[n * 16 + md]);
            w0[u] = sim_s[n]; w1[u] = sim_s[2048 + n]; ww[u] = sim_s[4096 + n];
        }
#pragma unroll
        for (int u = 3; u >= 0; u--) {
            float4 nv;
            nv.x = fmaf(v[u].x, fmaf(-ww[u], e4.x, 1.0f), ww[u] * a4.x);
            nv.y = fmaf(v[u].y, fmaf(-ww[u], e4.y, 1.0f), ww[u] * a4.y);
            nv.z = fmaf(v[u].z, fmaf(-ww[u], e4.z, 1.0f), ww[u] * a4.z);
            nv.w = fmaf(v[u].w, fmaf(-ww[u], e4.w, 1.0f), ww[u] * a4.w);
            __stcs(&mdst[nn[u] * 16 + md], nv);
            racc0[0] = fmaf(w0[u], v[u].x, racc0[0]);
            racc0[1] = fmaf(w0[u], v[u].y, racc0[1]);
            racc0[2] = fmaf(w0[u], v[u].z, racc0[2]);
            racc0[3] = fmaf(w0[u], v[u].w, racc0[3]);
            racc1[0] = fmaf(w1[u], v[u].x, racc1[0]);
            racc1[1] = fmaf(w1[u], v[u].y, racc1[1]);
            racc1[2] = fmaf(w1[u], v[u].z, racc1[2]);
            racc1[3] = fmaf(w1[u], v[u].w, racc1[3]);
        }
    }
#pragma unroll
    for (int u = 0; u < 4; u++) {
        racc0[u] += __shfl_xor_sync(0xffffffffu, racc0[u], 16);
        racc1[u] += __shfl_xor_sync(0xffffffffu, racc1[u], 16);
    }
    __syncthreads();   // all sim_s reads done; wgs free
    if (lane < 16) {
#pragma unroll
        for (int u = 0; u < 4; u++) {
            wgs[wrp * 128 + md * 4 + u] = racc0[u];
            wgs[wrp * 128 + 64 + md * 4 + u] = racc1[u];
        }
    }
    __syncthreads();

    // ---- epilogue (fused k5): out[b] = sigmoid([h_b, reads_b] @ outW^T + outb) ----
    // overlay: Wt = sim_s[0..4223] (128x33 tile), xs = sim_s[4224..4863]
    float* Wt = sim_s;
    float* xs = sim_s + 4224;
    if (tid < 128) {
        int h = tid >> 6, m = tid & 63;
        float sum = 0.f;
#pragma unroll
        for (int w = 0; w < 16; w++) sum += wgs[w * 128 + h * 64 + m];
        dout[OFF_READS + h * B_ * M_ + b * M_ + m] = sum;
        xs[512 + tid] = sum;
    }
    xs[tid] = dout[OFF_H + b * 512 + tid];

    int col = tid & 127, quart = tid >> 7;
    float acc = 0.f;
    for (int kt = 0; kt < 20; kt++) {
        __syncthreads();
        // stage outW[:, kt*32 .. kt*32+32) into Wt[128][33]
#pragma unroll
        for (int i = 0; i < 2; i++) {
            int idx = tid + 512 * i;           // 0..1023
            int o = idx >> 3, c4 = idx & 7;
            float4 wv = *(const float4*)(outW + (size_t)o * 640 + kt * 32 + c4 * 4);
            Wt[o * 33 + c4 * 4 + 0] = wv.x;
            Wt[o * 33 + c4 * 4 + 1] = wv.y;
            Wt[o * 33 + c4 * 4 + 2] = wv.z;
            Wt[o * 33 + c4 * 4 + 3] = wv.w;
        }
        __syncthreads();
#pragma unroll
        for (int kk = 0; kk < 8; kk++) {
            int k = quart * 8 + kk;
            acc = fmaf(Wt[col * 33 + k], xs[kt * 32 + k], acc);
        }
    }
    __syncthreads();
    wgs[quart * 128 + col] = acc;
    __syncthreads();
    if (tid < 128) {
        float total = wgs[tid] + wgs[128 + tid] + wgs[256 + tid] + wgs[384 + tid];
        dout[OFF_OUT + b * 128 + tid] = sigf(total + outb[tid]);
    }
}

extern "C" void kernel_launch(void* const* d_in, const int* in_sizes, int n_in,
                              void* d_out, int out_size) {
    const float* inp        = (const float*)d_in[0];
    const float* prev_reads = (const float*)d_in[1];
    const float* prev_h     = (const float*)d_in[2];
    const float* prev_c     = (const float*)d_in[3];
    const float* prev_ws    = (const float*)d_in[4];
    const float* memory     = (const float*)d_in[5];
    const float* W_ih       = (const float*)d_in[6];
    const float* W_hh       = (const float*)d_in[7];
    const float* b_lstm     = (const float*)d_in[8];
    const float* read_W     = (const float*)d_in[9];
    const float* read_b     = (const float*)d_in[10];
    const float* write_W    = (const float*)d_in[11];
    const float* write_b    = (const float*)d_in[12];
    const float* out_W      = (const float*)d_in[13];
    const float* out_b      = (const float*)d_in[14];
    float* dout = (float*)d_out;

    k1_gates<<<dim3(16, 4, 4), 256>>>(inp, prev_reads, prev_h, W_ih, W_hh);
    k1b_lstm<<<128, 256>>>(b_lstm, prev_c, dout);
    k2_p<<<dim3(6, 4, 8), 256>>>(read_W, write_W, dout);
    k345_fused<<<256, 512>>>(memory, prev_ws, read_b, write_b, out_W, out_b, dout);
}